// round 1
// baseline (speedup 1.0000x reference)
#include <cuda_runtime.h>
#include <math.h>

// Problem constants
// B=8, S=1024, D=1024, H=16, dh=64
#define PB 8
#define PS 1024
#define PD 1024
#define PH 16
#define PDH 64

// Scratch (allocation-free rule: __device__ globals)
__device__ float g_qkv[(size_t)PB * PS * 3 * PD];   // 96 MB  [B*S, 3D]
__device__ float g_attn[(size_t)PB * PS * PD];      // 32 MB  [B*S, D]

// ---------------------------------------------------------------------------
// SGEMM with bias: C[M,N] = A[M,K] @ B[K,N] + bias[N]
// Requires M%128==0, N%128==0, K%8==0.
// 256 threads, 128x128 block tile, 8x8 per-thread tile, BK=8.
// ---------------------------------------------------------------------------
__global__ __launch_bounds__(256) void sgemm_bias_kernel(
    const float* __restrict__ A, const float* __restrict__ Bm,
    const float* __restrict__ bias, float* __restrict__ C,
    int M, int N, int K)
{
    __shared__ float As[8][128];
    __shared__ float Bs[8][128];

    const int t  = threadIdx.x;
    const int bm = blockIdx.y * 128;
    const int bn = blockIdx.x * 128;
    const int ty = t / 16;           // 0..15 -> row group *8
    const int tx = t % 16;           // 0..15 -> col group *8

    // A-tile load mapping: thread -> (row, 4 consecutive k)
    const int ar = t / 2;            // 0..127
    const int ak = (t % 2) * 4;      // 0 or 4
    // B-tile load mapping: thread -> (k-row, 4 consecutive n)
    const int br = t / 32;           // 0..7
    const int bc = (t % 32) * 4;     // 0..124

    const float* Aptr = A + (size_t)(bm + ar) * K + ak;
    const float* Bptr = Bm + (size_t)br * N + bn + bc;

    float acc[8][8];
#pragma unroll
    for (int i = 0; i < 8; i++)
#pragma unroll
        for (int j = 0; j < 8; j++) acc[i][j] = 0.f;

    for (int k0 = 0; k0 < K; k0 += 8) {
        float4 av = *(const float4*)(Aptr + k0);
        float4 bv = *(const float4*)(Bptr + (size_t)k0 * N);
        __syncthreads();   // previous compute done before overwriting smem
        As[ak + 0][ar] = av.x;
        As[ak + 1][ar] = av.y;
        As[ak + 2][ar] = av.z;
        As[ak + 3][ar] = av.w;
        *(float4*)&Bs[br][bc] = bv;
        __syncthreads();

#pragma unroll
        for (int k = 0; k < 8; k++) {
            float a[8], b[8];
            *(float4*)(a)     = *(const float4*)&As[k][ty * 8];
            *(float4*)(a + 4) = *(const float4*)&As[k][ty * 8 + 4];
            *(float4*)(b)     = *(const float4*)&Bs[k][tx * 8];
            *(float4*)(b + 4) = *(const float4*)&Bs[k][tx * 8 + 4];
#pragma unroll
            for (int i = 0; i < 8; i++)
#pragma unroll
                for (int j = 0; j < 8; j++)
                    acc[i][j] = fmaf(a[i], b[j], acc[i][j]);
        }
    }

    // epilogue with bias
    float4 bb0 = *(const float4*)(bias + bn + tx * 8);
    float4 bb1 = *(const float4*)(bias + bn + tx * 8 + 4);
#pragma unroll
    for (int i = 0; i < 8; i++) {
        const int row = bm + ty * 8 + i;
        float* cp = C + (size_t)row * N + bn + tx * 8;
        float4 v0, v1;
        v0.x = acc[i][0] + bb0.x; v0.y = acc[i][1] + bb0.y;
        v0.z = acc[i][2] + bb0.z; v0.w = acc[i][3] + bb0.w;
        v1.x = acc[i][4] + bb1.x; v1.y = acc[i][5] + bb1.y;
        v1.z = acc[i][6] + bb1.z; v1.w = acc[i][7] + bb1.w;
        *(float4*)(cp)     = v0;
        *(float4*)(cp + 4) = v1;
    }
}

// ---------------------------------------------------------------------------
// Flash attention (fp32, causal). One block per (qtile of 64, b*h).
// 128 threads = 16x8 fragment grid; each thread: 4 rows x 8 cols.
// qkv layout: [B*S, 3*D], q at col 0, k at col D, v at col 2D; head h uses
// columns h*64 .. h*64+63 of each section.
// ---------------------------------------------------------------------------
__global__ __launch_bounds__(128) void flash_kernel(
    const float* __restrict__ qkv, float* __restrict__ out)
{
    extern __shared__ float sm[];
    float (*Qs)[64] = (float(*)[64])(sm);                 // [d][i]
    float (*Ks)[64] = (float(*)[64])(sm + 64 * 64);       // [d][j]
    float (*Vs)[64] = (float(*)[64])(sm + 2 * 64 * 64);   // [j][d]
    float (*Ps)[68] = (float(*)[68])(sm + 3 * 64 * 64);   // [j][i] padded

    const int t  = threadIdx.x;
    const int qt = blockIdx.x;            // 0..15
    const int bh = blockIdx.y;            // 0..127
    const int b  = bh / PH;
    const int h  = bh % PH;
    const int ti = t / 8;                 // 0..15
    const int tj = t % 8;                 // 0..7
    const int i0 = ti * 4;
    const int j0 = tj * 8;                // also d-group for PV / output
    const int qs = qt * 64;

    const size_t rowstride = 3 * PD;
    const float* qbase = qkv + (size_t)(b * PS) * rowstride + h * PDH;

    // Load Q tile transposed: Qs[d][i]
    {
        const int i  = t / 2;             // 0..63
        const int d0 = (t % 2) * 32;      // 0 or 32
        const float* qrow = qbase + (size_t)(qs + i) * rowstride + d0;
#pragma unroll
        for (int f = 0; f < 8; f++) {
            float4 v = *(const float4*)(qrow + f * 4);
            const int d = d0 + f * 4;
            Qs[d + 0][i] = v.x; Qs[d + 1][i] = v.y;
            Qs[d + 2][i] = v.z; Qs[d + 3][i] = v.w;
        }
    }

    float o[4][8];
    float m[4], l[4];
#pragma unroll
    for (int i = 0; i < 4; i++) {
        m[i] = -1e30f; l[i] = 0.f;
#pragma unroll
        for (int d = 0; d < 8; d++) o[i][d] = 0.f;
    }

    for (int kt = 0; kt <= qt; kt++) {
        __syncthreads();  // previous iteration's reads of Ks/Vs/Ps done
        // Load K tile transposed (Ks[d][j]) and V tile natural (Vs[j][d])
        {
            const int j  = t / 2;
            const int d0 = (t % 2) * 32;
            const float* krow = qkv + (size_t)(b * PS + kt * 64 + j) * rowstride
                                + PD + h * PDH + d0;
            const float* vrow = krow + PD;  // v section is D further
#pragma unroll
            for (int f = 0; f < 8; f++) {
                float4 kv = *(const float4*)(krow + f * 4);
                const int d = d0 + f * 4;
                Ks[d + 0][j] = kv.x; Ks[d + 1][j] = kv.y;
                Ks[d + 2][j] = kv.z; Ks[d + 3][j] = kv.w;
                float4 vv = *(const float4*)(vrow + f * 4);
                *(float4*)&Vs[j][d] = vv;
            }
        }
        __syncthreads();

        // S = Q @ K^T fragment (4x8), contract over d
        float s[4][8];
#pragma unroll
        for (int i = 0; i < 4; i++)
#pragma unroll
            for (int j = 0; j < 8; j++) s[i][j] = 0.f;

#pragma unroll
        for (int d = 0; d < 64; d++) {
            float a[4], bb[8];
            *(float4*)(a)      = *(const float4*)&Qs[d][i0];
            *(float4*)(bb)     = *(const float4*)&Ks[d][j0];
            *(float4*)(bb + 4) = *(const float4*)&Ks[d][j0 + 4];
#pragma unroll
            for (int i = 0; i < 4; i++)
#pragma unroll
                for (int j = 0; j < 8; j++)
                    s[i][j] = fmaf(a[i], bb[j], s[i][j]);
        }

        // scale + causal mask (diagonal tile only)
        const float sc = 0.125f;  // 1/sqrt(64)
        if (kt == qt) {
#pragma unroll
            for (int i = 0; i < 4; i++)
#pragma unroll
                for (int j = 0; j < 8; j++) {
                    const int gq = i0 + i;
                    const int gk = j0 + j;
                    s[i][j] = (gk <= gq) ? s[i][j] * sc : -1e30f;
                }
        } else {
#pragma unroll
            for (int i = 0; i < 4; i++)
#pragma unroll
                for (int j = 0; j < 8; j++) s[i][j] *= sc;
        }

        // online softmax per row (reduce across the 8 lanes sharing ti)
#pragma unroll
        for (int i = 0; i < 4; i++) {
            float rm = s[i][0];
#pragma unroll
            for (int j = 1; j < 8; j++) rm = fmaxf(rm, s[i][j]);
            rm = fmaxf(rm, __shfl_xor_sync(0xffffffffu, rm, 1));
            rm = fmaxf(rm, __shfl_xor_sync(0xffffffffu, rm, 2));
            rm = fmaxf(rm, __shfl_xor_sync(0xffffffffu, rm, 4));
            const float mn   = fmaxf(m[i], rm);
            const float corr = __expf(m[i] - mn);
            float rs = 0.f;
#pragma unroll
            for (int j = 0; j < 8; j++) {
                const float p = __expf(s[i][j] - mn);
                s[i][j] = p;
                rs += p;
            }
            rs += __shfl_xor_sync(0xffffffffu, rs, 1);
            rs += __shfl_xor_sync(0xffffffffu, rs, 2);
            rs += __shfl_xor_sync(0xffffffffu, rs, 4);
            l[i] = l[i] * corr + rs;
            m[i] = mn;
#pragma unroll
            for (int d = 0; d < 8; d++) o[i][d] *= corr;
        }

        // write P transposed: Ps[j][i]
#pragma unroll
        for (int j = 0; j < 8; j++) {
            float4 pv;
            pv.x = s[0][j]; pv.y = s[1][j]; pv.z = s[2][j]; pv.w = s[3][j];
            *(float4*)&Ps[j0 + j][i0] = pv;
        }
        __syncthreads();

        // O += P @ V, contract over j
#pragma unroll
        for (int j = 0; j < 64; j++) {
            float p4[4], v8[8];
            *(float4*)(p4)     = *(const float4*)&Ps[j][i0];
            *(float4*)(v8)     = *(const float4*)&Vs[j][j0];
            *(float4*)(v8 + 4) = *(const float4*)&Vs[j][j0 + 4];
#pragma unroll
            for (int i = 0; i < 4; i++)
#pragma unroll
                for (int d = 0; d < 8; d++)
                    o[i][d] = fmaf(p4[i], v8[d], o[i][d]);
        }
    }

    // epilogue: normalize and write [B*S, D] layout
#pragma unroll
    for (int i = 0; i < 4; i++) {
        const float inv = 1.f / l[i];
        const int row = qs + i0 + i;
        float* op = out + (size_t)(b * PS + row) * PD + h * PDH + j0;
        float4 v0, v1;
        v0.x = o[i][0] * inv; v0.y = o[i][1] * inv;
        v0.z = o[i][2] * inv; v0.w = o[i][3] * inv;
        v1.x = o[i][4] * inv; v1.y = o[i][5] * inv;
        v1.z = o[i][6] * inv; v1.w = o[i][7] * inv;
        *(float4*)(op)     = v0;
        *(float4*)(op + 4) = v1;
    }
}

// ---------------------------------------------------------------------------
// kernel_launch
// Inputs: x [8,1024,1024], W_qkv [1024,3072], b_qkv [3072],
//         W_out [1024,1024], b_out [1024]  -> out [8,1024,1024] fp32
// ---------------------------------------------------------------------------
extern "C" void kernel_launch(void* const* d_in, const int* in_sizes, int n_in,
                              void* d_out, int out_size)
{
    const float* x     = (const float*)d_in[0];
    const float* W_qkv = (const float*)d_in[1];
    const float* b_qkv = (const float*)d_in[2];
    const float* W_out = (const float*)d_in[3];
    const float* b_out = (const float*)d_in[4];
    float* out = (float*)d_out;

    float *qkv, *attn;
    cudaGetSymbolAddress((void**)&qkv, g_qkv);
    cudaGetSymbolAddress((void**)&attn, g_attn);

    const int M = PB * PS;  // 8192

    // 1) QKV projection: [8192,1024] @ [1024,3072] + b
    {
        dim3 grid(3 * PD / 128, M / 128);
        sgemm_bias_kernel<<<grid, 256>>>(x, W_qkv, b_qkv, qkv, M, 3 * PD, PD);
    }

    // 2) Flash attention
    {
        const int smem = (3 * 64 * 64 + 64 * 68) * (int)sizeof(float);  // 66560
        cudaFuncSetAttribute(flash_kernel,
                             cudaFuncAttributeMaxDynamicSharedMemorySize, smem);
        dim3 grid(PS / 64, PB * PH);
        flash_kernel<<<grid, 128, smem>>>(qkv, attn);
    }

    // 3) Output projection: [8192,1024] @ [1024,1024] + b
    {
        dim3 grid(PD / 128, M / 128);
        sgemm_bias_kernel<<<grid, 256>>>(attn, W_out, b_out, out, M, PD, PD);
    }
}

// round 2
// speedup vs baseline: 1.8069x; 1.8069x over previous
#include <cuda_runtime.h>
#include <math.h>
#include <cstdint>

// Problem constants: B=8, S=1024, D=1024, H=16, dh=64
#define PB 8
#define PS 1024
#define PD 1024
#define PH 16
#define PDH 64

// Scratch (allocation-free rule: __device__ globals)
__device__ float g_qkv[(size_t)PB * PS * 3 * PD];   // 96 MB  [B*S, 3D]
__device__ float g_attn[(size_t)PB * PS * PD];      // 32 MB  [B*S, D]

// ---------------------------------------------------------------------------
// TF32 tensor-core GEMM with bias: C[M,N] = A[M,K] @ B[K,N] + bias[N]
// Requires M%128==0, N%128==0, K%32==0.
// 256 threads = 8 warps (4x2), block tile 128x128, BK=32, warp tile 32x64.
// mma.sync.m16n8k8.tf32 with cvt.rna rounding on fragments.
// Double-buffered cp.async pipeline.
// ---------------------------------------------------------------------------
#define BM 128
#define BN 128
#define BK 32
#define ASTRIDE (BK + 4)    // 36 floats -> conflict-free A frag loads
#define BSTRIDE (BN + 8)    // 136 floats -> conflict-free B frag loads

__device__ __forceinline__ uint32_t f2tf32(float x) {
    uint32_t r;
    asm("cvt.rna.tf32.f32 %0, %1;" : "=r"(r) : "f"(x));
    return r;
}
__device__ __forceinline__ void cpa16(void* dst, const void* src) {
    uint32_t d = (uint32_t)__cvta_generic_to_shared(dst);
    asm volatile("cp.async.cg.shared.global [%0], [%1], 16;\n" :: "r"(d), "l"(src));
}

__global__ __launch_bounds__(256, 2) void tf32_gemm_bias(
    const float* __restrict__ A, const float* __restrict__ Bm,
    const float* __restrict__ bias, float* __restrict__ C,
    int M, int N, int K)
{
    extern __shared__ float sm[];
    float* As = sm;                       // [2][BM][ASTRIDE]
    float* Bs = sm + 2 * BM * ASTRIDE;    // [2][BK][BSTRIDE]

    const int t    = threadIdx.x;
    const int w    = t >> 5;
    const int lane = t & 31;
    const int bm   = blockIdx.y * BM;
    const int bn   = blockIdx.x * BN;
    const int wm   = (w >> 1) * 32;       // warp m offset
    const int wn   = (w & 1) * 64;        // warp n offset
    const int r    = lane >> 2;           // 0..7
    const int q    = lane & 3;            // 0..3

    const int KT = K / BK;

    // stage loader: A tile 128x32, B tile 32x128, 4 float4 chunks each per thread
    auto stage = [&](int kt, int buf) {
        const float* ga = A + (size_t)bm * K + kt * BK;
        float* sa = As + buf * BM * ASTRIDE;
#pragma unroll
        for (int i = 0; i < 4; i++) {
            int chunk = t + i * 256;
            int row = chunk >> 3, c4 = (chunk & 7) * 4;
            cpa16(sa + row * ASTRIDE + c4, ga + (size_t)row * K + c4);
        }
        const float* gb = Bm + (size_t)(kt * BK) * N + bn;
        float* sb = Bs + buf * BK * BSTRIDE;
#pragma unroll
        for (int i = 0; i < 4; i++) {
            int chunk = t + i * 256;
            int row = chunk >> 5, c4 = (chunk & 31) * 4;
            cpa16(sb + row * BSTRIDE + c4, gb + (size_t)row * N + c4);
        }
    };

    float c[2][8][4];
#pragma unroll
    for (int mf = 0; mf < 2; mf++)
#pragma unroll
        for (int nf = 0; nf < 8; nf++)
#pragma unroll
            for (int i = 0; i < 4; i++) c[mf][nf][i] = 0.f;

    stage(0, 0);
    asm volatile("cp.async.commit_group;\n");

    for (int kt = 0; kt < KT; kt++) {
        const int buf = kt & 1;
        if (kt + 1 < KT) {
            stage(kt + 1, buf ^ 1);
            asm volatile("cp.async.commit_group;\n");
            asm volatile("cp.async.wait_group 1;\n");
        } else {
            asm volatile("cp.async.wait_group 0;\n");
        }
        __syncthreads();

        const float* sa = As + buf * BM * ASTRIDE;
        const float* sb = Bs + buf * BK * BSTRIDE;

#pragma unroll
        for (int ks = 0; ks < 4; ks++) {
            const int k = ks * 8;
            uint32_t a[2][4];
#pragma unroll
            for (int mf = 0; mf < 2; mf++) {
                const int m0 = wm + mf * 16;
                a[mf][0] = f2tf32(sa[(m0 + r) * ASTRIDE + k + q]);
                a[mf][1] = f2tf32(sa[(m0 + r + 8) * ASTRIDE + k + q]);
                a[mf][2] = f2tf32(sa[(m0 + r) * ASTRIDE + k + q + 4]);
                a[mf][3] = f2tf32(sa[(m0 + r + 8) * ASTRIDE + k + q + 4]);
            }
#pragma unroll
            for (int nf = 0; nf < 8; nf++) {
                const int n0 = wn + nf * 8 + r;
                uint32_t b0 = f2tf32(sb[(k + q) * BSTRIDE + n0]);
                uint32_t b1 = f2tf32(sb[(k + q + 4) * BSTRIDE + n0]);
#pragma unroll
                for (int mf = 0; mf < 2; mf++) {
                    asm volatile(
                        "mma.sync.aligned.m16n8k8.row.col.f32.tf32.tf32.f32 "
                        "{%0,%1,%2,%3}, {%4,%5,%6,%7}, {%8,%9}, {%0,%1,%2,%3};\n"
                        : "+f"(c[mf][nf][0]), "+f"(c[mf][nf][1]),
                          "+f"(c[mf][nf][2]), "+f"(c[mf][nf][3])
                        : "r"(a[mf][0]), "r"(a[mf][1]), "r"(a[mf][2]), "r"(a[mf][3]),
                          "r"(b0), "r"(b1));
                }
            }
        }
        __syncthreads();
    }

    // epilogue with bias; c0/c1 -> (row, col..col+1), c2/c3 -> (row+8, ...)
#pragma unroll
    for (int mf = 0; mf < 2; mf++) {
        const int row0 = bm + wm + mf * 16 + r;
#pragma unroll
        for (int nf = 0; nf < 8; nf++) {
            const int col = bn + wn + nf * 8 + q * 2;
            float2 bi = *(const float2*)(bias + col);
            float2 v0 = make_float2(c[mf][nf][0] + bi.x, c[mf][nf][1] + bi.y);
            float2 v1 = make_float2(c[mf][nf][2] + bi.x, c[mf][nf][3] + bi.y);
            *(float2*)(C + (size_t)row0 * N + col)       = v0;
            *(float2*)(C + (size_t)(row0 + 8) * N + col) = v1;
        }
    }
}

// ---------------------------------------------------------------------------
// Flash attention (fp32, causal). One block per (qtile of 64, b*h).
// 128 threads = 16x8 fragment grid; each thread: 4 rows x 8 cols.
// ---------------------------------------------------------------------------
__global__ __launch_bounds__(128) void flash_kernel(
    const float* __restrict__ qkv, float* __restrict__ out)
{
    extern __shared__ float smf[];
    float (*Qs)[64] = (float(*)[64])(smf);
    float (*Ks)[64] = (float(*)[64])(smf + 64 * 64);
    float (*Vs)[64] = (float(*)[64])(smf + 2 * 64 * 64);
    float (*Ps)[68] = (float(*)[68])(smf + 3 * 64 * 64);

    const int t  = threadIdx.x;
    const int qt = blockIdx.x;
    const int bh = blockIdx.y;
    const int b  = bh / PH;
    const int h  = bh % PH;
    const int ti = t / 8;
    const int tj = t % 8;
    const int i0 = ti * 4;
    const int j0 = tj * 8;
    const int qs = qt * 64;

    const size_t rowstride = 3 * PD;
    const float* qbase = qkv + (size_t)(b * PS) * rowstride + h * PDH;

    {
        const int i  = t / 2;
        const int d0 = (t % 2) * 32;
        const float* qrow = qbase + (size_t)(qs + i) * rowstride + d0;
#pragma unroll
        for (int f = 0; f < 8; f++) {
            float4 v = *(const float4*)(qrow + f * 4);
            const int d = d0 + f * 4;
            Qs[d + 0][i] = v.x; Qs[d + 1][i] = v.y;
            Qs[d + 2][i] = v.z; Qs[d + 3][i] = v.w;
        }
    }

    float o[4][8];
    float m[4], l[4];
#pragma unroll
    for (int i = 0; i < 4; i++) {
        m[i] = -1e30f; l[i] = 0.f;
#pragma unroll
        for (int d = 0; d < 8; d++) o[i][d] = 0.f;
    }

    for (int kt = 0; kt <= qt; kt++) {
        __syncthreads();
        {
            const int j  = t / 2;
            const int d0 = (t % 2) * 32;
            const float* krow = qkv + (size_t)(b * PS + kt * 64 + j) * rowstride
                                + PD + h * PDH + d0;
            const float* vrow = krow + PD;
#pragma unroll
            for (int f = 0; f < 8; f++) {
                float4 kv = *(const float4*)(krow + f * 4);
                const int d = d0 + f * 4;
                Ks[d + 0][j] = kv.x; Ks[d + 1][j] = kv.y;
                Ks[d + 2][j] = kv.z; Ks[d + 3][j] = kv.w;
                float4 vv = *(const float4*)(vrow + f * 4);
                *(float4*)&Vs[j][d] = vv;
            }
        }
        __syncthreads();

        float s[4][8];
#pragma unroll
        for (int i = 0; i < 4; i++)
#pragma unroll
            for (int j = 0; j < 8; j++) s[i][j] = 0.f;

#pragma unroll
        for (int d = 0; d < 64; d++) {
            float a[4], bb[8];
            *(float4*)(a)      = *(const float4*)&Qs[d][i0];
            *(float4*)(bb)     = *(const float4*)&Ks[d][j0];
            *(float4*)(bb + 4) = *(const float4*)&Ks[d][j0 + 4];
#pragma unroll
            for (int i = 0; i < 4; i++)
#pragma unroll
                for (int j = 0; j < 8; j++)
                    s[i][j] = fmaf(a[i], bb[j], s[i][j]);
        }

        const float sc = 0.125f;
        if (kt == qt) {
#pragma unroll
            for (int i = 0; i < 4; i++)
#pragma unroll
                for (int j = 0; j < 8; j++) {
                    const int gq = i0 + i;
                    const int gk = j0 + j;
                    s[i][j] = (gk <= gq) ? s[i][j] * sc : -1e30f;
                }
        } else {
#pragma unroll
            for (int i = 0; i < 4; i++)
#pragma unroll
                for (int j = 0; j < 8; j++) s[i][j] *= sc;
        }

#pragma unroll
        for (int i = 0; i < 4; i++) {
            float rm = s[i][0];
#pragma unroll
            for (int j = 1; j < 8; j++) rm = fmaxf(rm, s[i][j]);
            rm = fmaxf(rm, __shfl_xor_sync(0xffffffffu, rm, 1));
            rm = fmaxf(rm, __shfl_xor_sync(0xffffffffu, rm, 2));
            rm = fmaxf(rm, __shfl_xor_sync(0xffffffffu, rm, 4));
            const float mn   = fmaxf(m[i], rm);
            const float corr = __expf(m[i] - mn);
            float rs = 0.f;
#pragma unroll
            for (int j = 0; j < 8; j++) {
                const float p = __expf(s[i][j] - mn);
                s[i][j] = p;
                rs += p;
            }
            rs += __shfl_xor_sync(0xffffffffu, rs, 1);
            rs += __shfl_xor_sync(0xffffffffu, rs, 2);
            rs += __shfl_xor_sync(0xffffffffu, rs, 4);
            l[i] = l[i] * corr + rs;
            m[i] = mn;
#pragma unroll
            for (int d = 0; d < 8; d++) o[i][d] *= corr;
        }

#pragma unroll
        for (int j = 0; j < 8; j++) {
            float4 pv;
            pv.x = s[0][j]; pv.y = s[1][j]; pv.z = s[2][j]; pv.w = s[3][j];
            *(float4*)&Ps[j0 + j][i0] = pv;
        }
        __syncthreads();

#pragma unroll
        for (int j = 0; j < 64; j++) {
            float p4[4], v8[8];
            *(float4*)(p4)     = *(const float4*)&Ps[j][i0];
            *(float4*)(v8)     = *(const float4*)&Vs[j][j0];
            *(float4*)(v8 + 4) = *(const float4*)&Vs[j][j0 + 4];
#pragma unroll
            for (int i = 0; i < 4; i++)
#pragma unroll
                for (int d = 0; d < 8; d++)
                    o[i][d] = fmaf(p4[i], v8[d], o[i][d]);
        }
    }

#pragma unroll
    for (int i = 0; i < 4; i++) {
        const float inv = 1.f / l[i];
        const int row = qs + i0 + i;
        float* op = out + (size_t)(b * PS + row) * PD + h * PDH + j0;
        float4 v0, v1;
        v0.x = o[i][0] * inv; v0.y = o[i][1] * inv;
        v0.z = o[i][2] * inv; v0.w = o[i][3] * inv;
        v1.x = o[i][4] * inv; v1.y = o[i][5] * inv;
        v1.z = o[i][6] * inv; v1.w = o[i][7] * inv;
        *(float4*)(op)     = v0;
        *(float4*)(op + 4) = v1;
    }
}

// ---------------------------------------------------------------------------
// kernel_launch
// ---------------------------------------------------------------------------
extern "C" void kernel_launch(void* const* d_in, const int* in_sizes, int n_in,
                              void* d_out, int out_size)
{
    const float* x     = (const float*)d_in[0];
    const float* W_qkv = (const float*)d_in[1];
    const float* b_qkv = (const float*)d_in[2];
    const float* W_out = (const float*)d_in[3];
    const float* b_out = (const float*)d_in[4];
    float* out = (float*)d_out;

    float *qkv, *attn;
    cudaGetSymbolAddress((void**)&qkv, g_qkv);
    cudaGetSymbolAddress((void**)&attn, g_attn);

    const int M = PB * PS;  // 8192
    const int gemm_smem = (2 * BM * ASTRIDE + 2 * BK * BSTRIDE) * (int)sizeof(float); // 71680

    static int configured = 0;
    if (!configured) {
        cudaFuncSetAttribute(tf32_gemm_bias,
                             cudaFuncAttributeMaxDynamicSharedMemorySize, gemm_smem);
        const int fl_smem = (3 * 64 * 64 + 64 * 68) * (int)sizeof(float);
        cudaFuncSetAttribute(flash_kernel,
                             cudaFuncAttributeMaxDynamicSharedMemorySize, fl_smem);
        configured = 1;
    }

    // 1) QKV projection: [8192,1024] @ [1024,3072] + b
    {
        dim3 grid(3 * PD / BN, M / BM);
        tf32_gemm_bias<<<grid, 256, gemm_smem>>>(x, W_qkv, b_qkv, qkv, M, 3 * PD, PD);
    }

    // 2) Flash attention
    {
        const int smem = (3 * 64 * 64 + 64 * 68) * (int)sizeof(float);  // 66560
        dim3 grid(PS / 64, PB * PH);
        flash_kernel<<<grid, 128, smem>>>(qkv, attn);
    }

    // 3) Output projection: [8192,1024] @ [1024,1024] + b
    {
        dim3 grid(PD / BN, M / BM);
        tf32_gemm_bias<<<grid, 256, gemm_smem>>>(attn, W_out, b_out, out, M, PD, PD);
    }
}

// round 3
// speedup vs baseline: 3.9066x; 2.1621x over previous
#include <cuda_runtime.h>
#include <math.h>
#include <cstdint>

// Problem constants: B=8, S=1024, D=1024, H=16, dh=64
#define PB 8
#define PS 1024
#define PD 1024
#define PH 16
#define PDH 64

// Scratch (allocation-free rule: __device__ globals)
__device__ float g_qkv[(size_t)PB * PS * 3 * PD];   // 96 MB  [B*S, 3D]
__device__ float g_attn[(size_t)PB * PS * PD];      // 32 MB  [B*S, D]

__device__ __forceinline__ uint32_t f2tf32(float x) {
    uint32_t r;
    asm("cvt.rna.tf32.f32 %0, %1;" : "=r"(r) : "f"(x));
    return r;
}
__device__ __forceinline__ void cpa16(void* dst, const void* src) {
    uint32_t d = (uint32_t)__cvta_generic_to_shared(dst);
    asm volatile("cp.async.cg.shared.global [%0], [%1], 16;\n" :: "r"(d), "l"(src));
}
__device__ __forceinline__ void mma_tf32(float c[4], const uint32_t a[4],
                                         uint32_t b0, uint32_t b1) {
    asm volatile(
        "mma.sync.aligned.m16n8k8.row.col.f32.tf32.tf32.f32 "
        "{%0,%1,%2,%3}, {%4,%5,%6,%7}, {%8,%9}, {%0,%1,%2,%3};\n"
        : "+f"(c[0]), "+f"(c[1]), "+f"(c[2]), "+f"(c[3])
        : "r"(a[0]), "r"(a[1]), "r"(a[2]), "r"(a[3]), "r"(b0), "r"(b1));
}

// ---------------------------------------------------------------------------
// TF32 tensor-core GEMM with bias (unchanged from round 2)
// ---------------------------------------------------------------------------
#define BM 128
#define BN 128
#define BK 32
#define ASTRIDE (BK + 4)
#define BSTRIDE (BN + 8)

__global__ __launch_bounds__(256, 2) void tf32_gemm_bias(
    const float* __restrict__ A, const float* __restrict__ Bm,
    const float* __restrict__ bias, float* __restrict__ C,
    int M, int N, int K)
{
    extern __shared__ float sm[];
    float* As = sm;
    float* Bs = sm + 2 * BM * ASTRIDE;

    const int t    = threadIdx.x;
    const int w    = t >> 5;
    const int lane = t & 31;
    const int bm   = blockIdx.y * BM;
    const int bn   = blockIdx.x * BN;
    const int wm   = (w >> 1) * 32;
    const int wn   = (w & 1) * 64;
    const int r    = lane >> 2;
    const int q    = lane & 3;

    const int KT = K / BK;

    auto stage = [&](int kt, int buf) {
        const float* ga = A + (size_t)bm * K + kt * BK;
        float* sa = As + buf * BM * ASTRIDE;
#pragma unroll
        for (int i = 0; i < 4; i++) {
            int chunk = t + i * 256;
            int row = chunk >> 3, c4 = (chunk & 7) * 4;
            cpa16(sa + row * ASTRIDE + c4, ga + (size_t)row * K + c4);
        }
        const float* gb = Bm + (size_t)(kt * BK) * N + bn;
        float* sb = Bs + buf * BK * BSTRIDE;
#pragma unroll
        for (int i = 0; i < 4; i++) {
            int chunk = t + i * 256;
            int row = chunk >> 5, c4 = (chunk & 31) * 4;
            cpa16(sb + row * BSTRIDE + c4, gb + (size_t)row * N + c4);
        }
    };

    float c[2][8][4];
#pragma unroll
    for (int mf = 0; mf < 2; mf++)
#pragma unroll
        for (int nf = 0; nf < 8; nf++)
#pragma unroll
            for (int i = 0; i < 4; i++) c[mf][nf][i] = 0.f;

    stage(0, 0);
    asm volatile("cp.async.commit_group;\n");

    for (int kt = 0; kt < KT; kt++) {
        const int buf = kt & 1;
        if (kt + 1 < KT) {
            stage(kt + 1, buf ^ 1);
            asm volatile("cp.async.commit_group;\n");
            asm volatile("cp.async.wait_group 1;\n");
        } else {
            asm volatile("cp.async.wait_group 0;\n");
        }
        __syncthreads();

        const float* sa = As + buf * BM * ASTRIDE;
        const float* sb = Bs + buf * BK * BSTRIDE;

#pragma unroll
        for (int ks = 0; ks < 4; ks++) {
            const int k = ks * 8;
            uint32_t a[2][4];
#pragma unroll
            for (int mf = 0; mf < 2; mf++) {
                const int m0 = wm + mf * 16;
                a[mf][0] = f2tf32(sa[(m0 + r) * ASTRIDE + k + q]);
                a[mf][1] = f2tf32(sa[(m0 + r + 8) * ASTRIDE + k + q]);
                a[mf][2] = f2tf32(sa[(m0 + r) * ASTRIDE + k + q + 4]);
                a[mf][3] = f2tf32(sa[(m0 + r + 8) * ASTRIDE + k + q + 4]);
            }
#pragma unroll
            for (int nf = 0; nf < 8; nf++) {
                const int n0 = wn + nf * 8 + r;
                uint32_t b0 = f2tf32(sb[(k + q) * BSTRIDE + n0]);
                uint32_t b1 = f2tf32(sb[(k + q + 4) * BSTRIDE + n0]);
#pragma unroll
                for (int mf = 0; mf < 2; mf++)
                    mma_tf32(c[mf][nf], a[mf], b0, b1);
            }
        }
        __syncthreads();
    }

#pragma unroll
    for (int mf = 0; mf < 2; mf++) {
        const int row0 = bm + wm + mf * 16 + r;
#pragma unroll
        for (int nf = 0; nf < 8; nf++) {
            const int col = bn + wn + nf * 8 + q * 2;
            float2 bi = *(const float2*)(bias + col);
            float2 v0 = make_float2(c[mf][nf][0] + bi.x, c[mf][nf][1] + bi.y);
            float2 v1 = make_float2(c[mf][nf][2] + bi.x, c[mf][nf][3] + bi.y);
            *(float2*)(C + (size_t)row0 * N + col)       = v0;
            *(float2*)(C + (size_t)(row0 + 8) * N + col) = v1;
        }
    }
}

// ---------------------------------------------------------------------------
// Tensor-core flash attention (tf32 mma, fp32 accum, causal).
// Grid (8 qtiles, 128 b*h). Block 256 threads = 8 warps; warp owns 16 q rows.
// k-tile 64. K/V double-buffered via cp.async.
// smem layout (floats): Ks[2][64][68] | Vs[2][64][72] | Ps[128][68]
// ---------------------------------------------------------------------------
#define KSTR 68
#define VSTR 72
#define PSTR 68
#define FL_SMEM_FLOATS (2 * 64 * KSTR + 2 * 64 * VSTR + 128 * PSTR)

__global__ __launch_bounds__(256) void flash_tc_kernel(
    const float* __restrict__ qkv, float* __restrict__ out)
{
    extern __shared__ float sm[];
    float* KsBase = sm;                              // [2][64][KSTR]
    float* VsBase = sm + 2 * 64 * KSTR;              // [2][64][VSTR]
    float* Ps     = sm + 2 * 64 * KSTR + 2 * 64 * VSTR; // [128][PSTR]

    const int t    = threadIdx.x;
    const int w    = t >> 5;
    const int lane = t & 31;
    const int r    = lane >> 2;   // 0..7
    const int q    = lane & 3;    // 0..3
    const int qt   = blockIdx.x;  // 0..7
    const int bh   = blockIdx.y;  // 0..127
    const int b    = bh / PH;
    const int h    = bh % PH;

    const int qbase = qt * 128 + w * 16;  // this warp's first q row
    const size_t rowstride = 3 * PD;

    // staging bases (K section at +PD, V at +2*PD)
    const float* kbase = qkv + (size_t)(b * PS) * rowstride + PD + h * PDH;
    const float* vbase = kbase + PD;

    // --- load Q fragments (pre-scaled by 1/sqrt(64)=0.125), keep in regs ---
    uint32_t qa[8][4];
    {
        const float* qp = qkv + (size_t)(b * PS + qbase) * rowstride + h * PDH;
#pragma unroll
        for (int kf = 0; kf < 8; kf++) {
            const int d = kf * 8;
            qa[kf][0] = f2tf32(0.125f * qp[(size_t)r * rowstride + d + q]);
            qa[kf][1] = f2tf32(0.125f * qp[(size_t)(r + 8) * rowstride + d + q]);
            qa[kf][2] = f2tf32(0.125f * qp[(size_t)r * rowstride + d + q + 4]);
            qa[kf][3] = f2tf32(0.125f * qp[(size_t)(r + 8) * rowstride + d + q + 4]);
        }
    }

    float oc[8][4];
#pragma unroll
    for (int nf = 0; nf < 8; nf++)
#pragma unroll
        for (int i = 0; i < 4; i++) oc[nf][i] = 0.f;
    float m0 = -1e30f, m1 = -1e30f, l0 = 0.f, l1 = 0.f;

    const int nkt = 2 * qt + 2;

    // stage: 64x64 K and V tiles. thread -> 4 chunks each; 16 lanes per row.
    auto stage = [&](int kt, int buf) {
        float* ks = KsBase + buf * 64 * KSTR;
        float* vs = VsBase + buf * 64 * VSTR;
        const int c4 = (t & 15) * 4;
        const int j0s = t >> 4;  // 0..15
#pragma unroll
        for (int i = 0; i < 4; i++) {
            const int j = j0s + i * 16;
            const size_t grow = (size_t)(kt * 64 + j) * rowstride;
            cpa16(ks + j * KSTR + c4, kbase + grow + c4);
            cpa16(vs + j * VSTR + c4, vbase + grow + c4);
        }
    };

    stage(0, 0);
    asm volatile("cp.async.commit_group;\n");

    for (int kt = 0; kt < nkt; kt++) {
        const int buf = kt & 1;
        if (kt + 1 < nkt) {
            stage(kt + 1, buf ^ 1);
            asm volatile("cp.async.commit_group;\n");
            asm volatile("cp.async.wait_group 1;\n");
        } else {
            asm volatile("cp.async.wait_group 0;\n");
        }
        __syncthreads();

        const int gk0 = kt * 64;
        if (gk0 <= qbase + 15) {   // any visible element for this warp?
            const float* ks = KsBase + buf * 64 * KSTR;
            const float* vs = VsBase + buf * 64 * VSTR;

            // ---- S = Q @ K^T  (per warp 16x64) ----
            float s[8][4];
#pragma unroll
            for (int nf = 0; nf < 8; nf++)
#pragma unroll
                for (int i = 0; i < 4; i++) s[nf][i] = 0.f;

#pragma unroll
            for (int kf = 0; kf < 8; kf++) {
                const int d = kf * 8;
#pragma unroll
                for (int nf = 0; nf < 8; nf++) {
                    // B=K^T col-major: b0=K[j=nf*8+r][d+q], b1=K[j][d+q+4]
                    const float* kr = ks + (nf * 8 + r) * KSTR + d;
                    uint32_t b0 = f2tf32(kr[q]);
                    uint32_t b1 = f2tf32(kr[q + 4]);
                    mma_tf32(s[nf], qa[kf], b0, b1);
                }
            }

            // ---- causal mask (only on straddling tiles) ----
            if (gk0 + 63 > qbase) {
                const int gq0 = qbase + r;
                const int gq1 = gq0 + 8;
#pragma unroll
                for (int nf = 0; nf < 8; nf++) {
                    const int gk = gk0 + nf * 8 + 2 * q;
                    if (gk > gq0)     s[nf][0] = -1e30f;
                    if (gk + 1 > gq0) s[nf][1] = -1e30f;
                    if (gk > gq1)     s[nf][2] = -1e30f;
                    if (gk + 1 > gq1) s[nf][3] = -1e30f;
                }
            }

            // ---- online softmax (rows r and r+8) ----
            float rm0 = s[0][0], rm1 = s[0][2];
#pragma unroll
            for (int nf = 0; nf < 8; nf++) {
                rm0 = fmaxf(rm0, fmaxf(s[nf][0], s[nf][1]));
                rm1 = fmaxf(rm1, fmaxf(s[nf][2], s[nf][3]));
            }
            rm0 = fmaxf(rm0, __shfl_xor_sync(0xffffffffu, rm0, 1));
            rm0 = fmaxf(rm0, __shfl_xor_sync(0xffffffffu, rm0, 2));
            rm1 = fmaxf(rm1, __shfl_xor_sync(0xffffffffu, rm1, 1));
            rm1 = fmaxf(rm1, __shfl_xor_sync(0xffffffffu, rm1, 2));
            const float mn0 = fmaxf(m0, rm0);
            const float mn1 = fmaxf(m1, rm1);
            const float corr0 = __expf(m0 - mn0);
            const float corr1 = __expf(m1 - mn1);
            float rs0 = 0.f, rs1 = 0.f;
#pragma unroll
            for (int nf = 0; nf < 8; nf++) {
                s[nf][0] = __expf(s[nf][0] - mn0);
                s[nf][1] = __expf(s[nf][1] - mn0);
                s[nf][2] = __expf(s[nf][2] - mn1);
                s[nf][3] = __expf(s[nf][3] - mn1);
                rs0 += s[nf][0] + s[nf][1];
                rs1 += s[nf][2] + s[nf][3];
            }
            rs0 += __shfl_xor_sync(0xffffffffu, rs0, 1);
            rs0 += __shfl_xor_sync(0xffffffffu, rs0, 2);
            rs1 += __shfl_xor_sync(0xffffffffu, rs1, 1);
            rs1 += __shfl_xor_sync(0xffffffffu, rs1, 2);
            l0 = l0 * corr0 + rs0;  m0 = mn0;
            l1 = l1 * corr1 + rs1;  m1 = mn1;
#pragma unroll
            for (int nf = 0; nf < 8; nf++) {
                oc[nf][0] *= corr0; oc[nf][1] *= corr0;
                oc[nf][2] *= corr1; oc[nf][3] *= corr1;
            }

            // ---- P -> per-warp smem (warp-private rows) ----
            float* prow0 = Ps + (w * 16 + r) * PSTR;
            float* prow1 = prow0 + 8 * PSTR;
#pragma unroll
            for (int nf = 0; nf < 8; nf++) {
                const int col = nf * 8 + 2 * q;
                *(float2*)(prow0 + col) = make_float2(s[nf][0], s[nf][1]);
                *(float2*)(prow1 + col) = make_float2(s[nf][2], s[nf][3]);
            }
            __syncwarp();

            // ---- O += P @ V ----
#pragma unroll
            for (int kf = 0; kf < 8; kf++) {
                const int j = kf * 8;
                uint32_t pa[4];
                pa[0] = f2tf32(prow0[j + q]);
                pa[1] = f2tf32(prow1[j + q]);
                pa[2] = f2tf32(prow0[j + q + 4]);
                pa[3] = f2tf32(prow1[j + q + 4]);
#pragma unroll
                for (int nf = 0; nf < 8; nf++) {
                    // B=V: b0=V[j+q][d=nf*8+r], b1=V[j+q+4][d]
                    const float* vr = vs + (j + q) * VSTR + nf * 8 + r;
                    uint32_t b0 = f2tf32(vr[0]);
                    uint32_t b1 = f2tf32(vr[4 * VSTR]);
                    mma_tf32(oc[nf], pa, b0, b1);
                }
            }
        }
        __syncthreads();
    }

    // ---- epilogue: normalize, write [B*S, D] ----
    const float inv0 = 1.f / l0;
    const float inv1 = 1.f / l1;
    float* o0 = out + (size_t)(b * PS + qbase + r) * PD + h * PDH;
    float* o1 = o0 + 8 * PD;
#pragma unroll
    for (int nf = 0; nf < 8; nf++) {
        const int col = nf * 8 + 2 * q;
        *(float2*)(o0 + col) = make_float2(oc[nf][0] * inv0, oc[nf][1] * inv0);
        *(float2*)(o1 + col) = make_float2(oc[nf][2] * inv1, oc[nf][3] * inv1);
    }
}

// ---------------------------------------------------------------------------
// kernel_launch
// ---------------------------------------------------------------------------
extern "C" void kernel_launch(void* const* d_in, const int* in_sizes, int n_in,
                              void* d_out, int out_size)
{
    const float* x     = (const float*)d_in[0];
    const float* W_qkv = (const float*)d_in[1];
    const float* b_qkv = (const float*)d_in[2];
    const float* W_out = (const float*)d_in[3];
    const float* b_out = (const float*)d_in[4];
    float* out = (float*)d_out;

    float *qkv, *attn;
    cudaGetSymbolAddress((void**)&qkv, g_qkv);
    cudaGetSymbolAddress((void**)&attn, g_attn);

    const int M = PB * PS;  // 8192
    const int gemm_smem = (2 * BM * ASTRIDE + 2 * BK * BSTRIDE) * (int)sizeof(float);
    const int fl_smem = FL_SMEM_FLOATS * (int)sizeof(float);  // 106496

    static int configured = 0;
    if (!configured) {
        cudaFuncSetAttribute(tf32_gemm_bias,
                             cudaFuncAttributeMaxDynamicSharedMemorySize, gemm_smem);
        cudaFuncSetAttribute(flash_tc_kernel,
                             cudaFuncAttributeMaxDynamicSharedMemorySize, fl_smem);
        configured = 1;
    }

    // 1) QKV projection: [8192,1024] @ [1024,3072] + b
    {
        dim3 grid(3 * PD / BN, M / BM);
        tf32_gemm_bias<<<grid, 256, gemm_smem>>>(x, W_qkv, b_qkv, qkv, M, 3 * PD, PD);
    }

    // 2) Tensor-core flash attention
    {
        dim3 grid(PS / 128, PB * PH);
        flash_tc_kernel<<<grid, 256, fl_smem>>>(qkv, attn);
    }

    // 3) Output projection: [8192,1024] @ [1024,1024] + b
    {
        dim3 grid(PD / BN, M / BM);
        tf32_gemm_bias<<<grid, 256, gemm_smem>>>(attn, W_out, b_out, out, M, PD, PD);
    }
}

// round 4
// speedup vs baseline: 4.0655x; 1.0407x over previous
#include <cuda_runtime.h>
#include <math.h>
#include <cstdint>

// Problem constants: B=8, S=1024, D=1024, H=16, dh=64
#define PB 8
#define PS 1024
#define PD 1024
#define PH 16
#define PDH 64

// Scratch (allocation-free rule: __device__ globals)
__device__ float g_qkv[(size_t)PB * PS * 3 * PD];   // 96 MB  [B*S, 3D]
__device__ float g_attn[(size_t)PB * PS * PD];      // 32 MB  [B*S, D]
__device__ float g_xr[(size_t)PB * PS * PD];        // 32 MB  x rounded
__device__ float g_wqr[(size_t)PD * 3 * PD];        // 12 MB  W_qkv rounded
__device__ float g_wor[(size_t)PD * PD];            //  4 MB  W_out rounded

__device__ __forceinline__ uint32_t f2tf32(float x) {
    uint32_t r;
    asm("cvt.rna.tf32.f32 %0, %1;" : "=r"(r) : "f"(x));
    return r;
}
__device__ __forceinline__ float rnd_tf32(float x) {
    return __uint_as_float(f2tf32(x));
}
__device__ __forceinline__ void cpa16(void* dst, const void* src) {
    uint32_t d = (uint32_t)__cvta_generic_to_shared(dst);
    asm volatile("cp.async.cg.shared.global [%0], [%1], 16;\n" :: "r"(d), "l"(src));
}
__device__ __forceinline__ void mma_tf32(float c[4], const uint32_t a[4],
                                         uint32_t b0, uint32_t b1) {
    asm volatile(
        "mma.sync.aligned.m16n8k8.row.col.f32.tf32.tf32.f32 "
        "{%0,%1,%2,%3}, {%4,%5,%6,%7}, {%8,%9}, {%0,%1,%2,%3};\n"
        : "+f"(c[0]), "+f"(c[1]), "+f"(c[2]), "+f"(c[3])
        : "r"(a[0]), "r"(a[1]), "r"(a[2]), "r"(a[3]), "r"(b0), "r"(b1));
}
__device__ __forceinline__ void ldsm_x4(uint32_t r[4], const float* p) {
    uint32_t addr = (uint32_t)__cvta_generic_to_shared(p);
    asm volatile("ldmatrix.sync.aligned.m8n8.x4.shared.b16 {%0,%1,%2,%3}, [%4];\n"
                 : "=r"(r[0]), "=r"(r[1]), "=r"(r[2]), "=r"(r[3]) : "r"(addr));
}

// ---------------------------------------------------------------------------
// Elementwise tf32 rounding pass (float4 grid-stride)
// ---------------------------------------------------------------------------
__global__ void round_tf32_kernel(const float* __restrict__ in,
                                  float* __restrict__ out, int n4)
{
    int i = blockIdx.x * blockDim.x + threadIdx.x;
    for (; i < n4; i += gridDim.x * blockDim.x) {
        float4 v = ((const float4*)in)[i];
        v.x = rnd_tf32(v.x); v.y = rnd_tf32(v.y);
        v.z = rnd_tf32(v.z); v.w = rnd_tf32(v.w);
        ((float4*)out)[i] = v;
    }
}

// ---------------------------------------------------------------------------
// TF32 tensor-core GEMM with bias. Inputs pre-rounded to tf32.
// C[M,N] = A[M,K] @ B[K,N] + bias[N]; optional tf32 rounding of C (RND).
// 256 threads = 8 warps (2m x 4n), block tile 128x128, BK=32, warp tile 64x32.
// A fragments via ldmatrix.x4; B fragments raw scalar LDS (no cvt).
// 3-stage cp.async pipeline.
// ---------------------------------------------------------------------------
#define BM 128
#define BN 128
#define BK 32
#define NSTAGE 3
#define ASTRIDE (BK + 4)    // 36 floats (144B, 16B-aligned rows)
#define BSTRIDE (BN + 8)    // 136 floats
#define GEMM_SMEM_FLOATS (NSTAGE * (BM * ASTRIDE + BK * BSTRIDE))

template<int RND>
__global__ __launch_bounds__(256, 2) void tf32_gemm_bias(
    const float* __restrict__ A, const float* __restrict__ Bm,
    const float* __restrict__ bias, float* __restrict__ C,
    int M, int N, int K)
{
    extern __shared__ float sm[];

    const int t    = threadIdx.x;
    const int w    = t >> 5;
    const int lane = t & 31;
    const int bm   = blockIdx.y * BM;
    const int bn   = blockIdx.x * BN;
    const int wm   = (w & 1) * 64;        // warp m offset (64 rows)
    const int wn   = (w >> 1) * 32;       // warp n offset (32 cols)
    const int r    = lane >> 2;           // 0..7
    const int q    = lane & 3;            // 0..3

    const int KT = K / BK;

    auto stage = [&](int kt, int buf) {
        float* sa = sm + buf * (BM * ASTRIDE + BK * BSTRIDE);
        float* sb = sa + BM * ASTRIDE;
        const float* ga = A + (size_t)bm * K + kt * BK;
#pragma unroll
        for (int i = 0; i < 4; i++) {
            int chunk = t + i * 256;
            int row = chunk >> 3, c4 = (chunk & 7) * 4;
            cpa16(sa + row * ASTRIDE + c4, ga + (size_t)row * K + c4);
        }
        const float* gb = Bm + (size_t)(kt * BK) * N + bn;
#pragma unroll
        for (int i = 0; i < 4; i++) {
            int chunk = t + i * 256;
            int row = chunk >> 5, c4 = (chunk & 31) * 4;
            cpa16(sb + row * BSTRIDE + c4, gb + (size_t)row * N + c4);
        }
    };

    float c[4][4][4];
#pragma unroll
    for (int mf = 0; mf < 4; mf++)
#pragma unroll
        for (int nf = 0; nf < 4; nf++)
#pragma unroll
            for (int i = 0; i < 4; i++) c[mf][nf][i] = 0.f;

    stage(0, 0);
    asm volatile("cp.async.commit_group;\n");
    stage(1, 1);
    asm volatile("cp.async.commit_group;\n");

    // ldmatrix lane constants for A fragments
    const int lrow = lane & 15;                 // row within 16-row fragment
    const int lkof = (lane & 16) ? 4 : 0;       // k offset (lo/hi half)

    for (int kt = 0; kt < KT; kt++) {
        const int buf = kt % NSTAGE;
        if (kt + 1 < KT) {
            asm volatile("cp.async.wait_group 1;\n");
        } else {
            asm volatile("cp.async.wait_group 0;\n");
        }
        __syncthreads();
        if (kt + 2 < KT) {
            stage(kt + 2, (kt + 2) % NSTAGE);
            asm volatile("cp.async.commit_group;\n");
        }

        const float* sa = sm + buf * (BM * ASTRIDE + BK * BSTRIDE);
        const float* sb = sa + BM * ASTRIDE;

#pragma unroll
        for (int ks = 0; ks < 4; ks++) {
            const int k = ks * 8;
            uint32_t a[4][4];
#pragma unroll
            for (int mf = 0; mf < 4; mf++)
                ldsm_x4(a[mf], sa + (wm + mf * 16 + lrow) * ASTRIDE + k + lkof);

            uint32_t b0[4], b1[4];
#pragma unroll
            for (int nf = 0; nf < 4; nf++) {
                const int n0 = wn + nf * 8 + r;
                b0[nf] = __float_as_uint(sb[(k + q) * BSTRIDE + n0]);
                b1[nf] = __float_as_uint(sb[(k + q + 4) * BSTRIDE + n0]);
            }
#pragma unroll
            for (int nf = 0; nf < 4; nf++)
#pragma unroll
                for (int mf = 0; mf < 4; mf++)
                    mma_tf32(c[mf][nf], a[mf], b0[nf], b1[nf]);
        }
    }

#pragma unroll
    for (int mf = 0; mf < 4; mf++) {
        const int row0 = bm + wm + mf * 16 + r;
#pragma unroll
        for (int nf = 0; nf < 4; nf++) {
            const int col = bn + wn + nf * 8 + q * 2;
            float2 bi = *(const float2*)(bias + col);
            float2 v0 = make_float2(c[mf][nf][0] + bi.x, c[mf][nf][1] + bi.y);
            float2 v1 = make_float2(c[mf][nf][2] + bi.x, c[mf][nf][3] + bi.y);
            if (RND) {
                v0.x = rnd_tf32(v0.x); v0.y = rnd_tf32(v0.y);
                v1.x = rnd_tf32(v1.x); v1.y = rnd_tf32(v1.y);
            }
            *(float2*)(C + (size_t)row0 * N + col)       = v0;
            *(float2*)(C + (size_t)(row0 + 8) * N + col) = v1;
        }
    }
}

// ---------------------------------------------------------------------------
// Tensor-core flash attention (tf32 mma, fp32 accum, causal).
// qkv is pre-rounded tf32. K fragments via ldmatrix; V scalar raw LDS.
// Output stored tf32-rounded (feeds pre-rounded A of out-projection).
// Grid (8 qtiles, 128 b*h). Block 256 = 8 warps; warp owns 16 q rows.
// smem (floats): Ks[2][64][68] | Vs[2][64][72] | Ps[128][68]
// ---------------------------------------------------------------------------
#define KSTR 68
#define VSTR 72
#define PSTR 68
#define FL_SMEM_FLOATS (2 * 64 * KSTR + 2 * 64 * VSTR + 128 * PSTR)

__global__ __launch_bounds__(256) void flash_tc_kernel(
    const float* __restrict__ qkv, float* __restrict__ out)
{
    extern __shared__ float sm[];
    float* KsBase = sm;
    float* VsBase = sm + 2 * 64 * KSTR;
    float* Ps     = sm + 2 * 64 * KSTR + 2 * 64 * VSTR;

    const int t    = threadIdx.x;
    const int w    = t >> 5;
    const int lane = t & 31;
    const int r    = lane >> 2;
    const int q    = lane & 3;
    const int qt   = blockIdx.x;
    const int bh   = blockIdx.y;
    const int b    = bh / PH;
    const int h    = bh % PH;

    const int qbase = qt * 128 + w * 16;
    const size_t rowstride = 3 * PD;

    const float* kbase = qkv + (size_t)(b * PS) * rowstride + PD + h * PDH;
    const float* vbase = kbase + PD;

    // Q fragments (raw bits; x0.125 stays exact tf32 since it's a pow2 scale)
    uint32_t qa[8][4];
    {
        const float* qp = qkv + (size_t)(b * PS + qbase) * rowstride + h * PDH;
#pragma unroll
        for (int kf = 0; kf < 8; kf++) {
            const int d = kf * 8;
            qa[kf][0] = __float_as_uint(0.125f * qp[(size_t)r * rowstride + d + q]);
            qa[kf][1] = __float_as_uint(0.125f * qp[(size_t)(r + 8) * rowstride + d + q]);
            qa[kf][2] = __float_as_uint(0.125f * qp[(size_t)r * rowstride + d + q + 4]);
            qa[kf][3] = __float_as_uint(0.125f * qp[(size_t)(r + 8) * rowstride + d + q + 4]);
        }
    }

    float oc[8][4];
#pragma unroll
    for (int nf = 0; nf < 8; nf++)
#pragma unroll
        for (int i = 0; i < 4; i++) oc[nf][i] = 0.f;
    float m0 = -1e30f, m1 = -1e30f, l0 = 0.f, l1 = 0.f;

    const int nkt = 2 * qt + 2;

    auto stage = [&](int kt, int buf) {
        float* ks = KsBase + buf * 64 * KSTR;
        float* vs = VsBase + buf * 64 * VSTR;
        const int c4 = (t & 15) * 4;
        const int j0s = t >> 4;
#pragma unroll
        for (int i = 0; i < 4; i++) {
            const int j = j0s + i * 16;
            const size_t grow = (size_t)(kt * 64 + j) * rowstride;
            cpa16(ks + j * KSTR + c4, kbase + grow + c4);
            cpa16(vs + j * VSTR + c4, vbase + grow + c4);
        }
    };

    stage(0, 0);
    asm volatile("cp.async.commit_group;\n");

    // ldmatrix lane constants for K fragments
    const int kjofs = ((lane & 16) ? 8 : 0) + (lane & 7);  // row within 16-j pair
    const int kdofs = (lane & 8) ? 4 : 0;                  // d lo/hi half

    for (int kt = 0; kt < nkt; kt++) {
        const int buf = kt & 1;
        if (kt + 1 < nkt) {
            stage(kt + 1, buf ^ 1);
            asm volatile("cp.async.commit_group;\n");
            asm volatile("cp.async.wait_group 1;\n");
        } else {
            asm volatile("cp.async.wait_group 0;\n");
        }
        __syncthreads();

        const int gk0 = kt * 64;
        if (gk0 <= qbase + 15) {
            const float* ks = KsBase + buf * 64 * KSTR;
            const float* vs = VsBase + buf * 64 * VSTR;

            // ---- S = Q @ K^T ----
            float s[8][4];
#pragma unroll
            for (int nf = 0; nf < 8; nf++)
#pragma unroll
                for (int i = 0; i < 4; i++) s[nf][i] = 0.f;

#pragma unroll
            for (int kf = 0; kf < 8; kf++) {
                const int d = kf * 8;
#pragma unroll
                for (int p = 0; p < 4; p++) {
                    uint32_t kb[4];  // {b0(2p), b1(2p), b0(2p+1), b1(2p+1)}
                    ldsm_x4(kb, ks + (p * 16 + kjofs) * KSTR + d + kdofs);
                    mma_tf32(s[2 * p],     qa[kf], kb[0], kb[1]);
                    mma_tf32(s[2 * p + 1], qa[kf], kb[2], kb[3]);
                }
            }

            // ---- causal mask ----
            if (gk0 + 63 > qbase) {
                const int gq0 = qbase + r;
                const int gq1 = gq0 + 8;
#pragma unroll
                for (int nf = 0; nf < 8; nf++) {
                    const int gk = gk0 + nf * 8 + 2 * q;
                    if (gk > gq0)     s[nf][0] = -1e30f;
                    if (gk + 1 > gq0) s[nf][1] = -1e30f;
                    if (gk > gq1)     s[nf][2] = -1e30f;
                    if (gk + 1 > gq1) s[nf][3] = -1e30f;
                }
            }

            // ---- online softmax ----
            float rm0 = s[0][0], rm1 = s[0][2];
#pragma unroll
            for (int nf = 0; nf < 8; nf++) {
                rm0 = fmaxf(rm0, fmaxf(s[nf][0], s[nf][1]));
                rm1 = fmaxf(rm1, fmaxf(s[nf][2], s[nf][3]));
            }
            rm0 = fmaxf(rm0, __shfl_xor_sync(0xffffffffu, rm0, 1));
            rm0 = fmaxf(rm0, __shfl_xor_sync(0xffffffffu, rm0, 2));
            rm1 = fmaxf(rm1, __shfl_xor_sync(0xffffffffu, rm1, 1));
            rm1 = fmaxf(rm1, __shfl_xor_sync(0xffffffffu, rm1, 2));
            const float mn0 = fmaxf(m0, rm0);
            const float mn1 = fmaxf(m1, rm1);
            const float corr0 = __expf(m0 - mn0);
            const float corr1 = __expf(m1 - mn1);
            float rs0 = 0.f, rs1 = 0.f;
#pragma unroll
            for (int nf = 0; nf < 8; nf++) {
                s[nf][0] = __expf(s[nf][0] - mn0);
                s[nf][1] = __expf(s[nf][1] - mn0);
                s[nf][2] = __expf(s[nf][2] - mn1);
                s[nf][3] = __expf(s[nf][3] - mn1);
                rs0 += s[nf][0] + s[nf][1];
                rs1 += s[nf][2] + s[nf][3];
            }
            rs0 += __shfl_xor_sync(0xffffffffu, rs0, 1);
            rs0 += __shfl_xor_sync(0xffffffffu, rs0, 2);
            rs1 += __shfl_xor_sync(0xffffffffu, rs1, 1);
            rs1 += __shfl_xor_sync(0xffffffffu, rs1, 2);
            l0 = l0 * corr0 + rs0;  m0 = mn0;
            l1 = l1 * corr1 + rs1;  m1 = mn1;
#pragma unroll
            for (int nf = 0; nf < 8; nf++) {
                oc[nf][0] *= corr0; oc[nf][1] *= corr0;
                oc[nf][2] *= corr1; oc[nf][3] *= corr1;
            }

            // ---- P -> warp-private smem (tf32-rounded at store) ----
            float* prow0 = Ps + (w * 16 + r) * PSTR;
            float* prow1 = prow0 + 8 * PSTR;
#pragma unroll
            for (int nf = 0; nf < 8; nf++) {
                const int col = nf * 8 + 2 * q;
                *(float2*)(prow0 + col) = make_float2(rnd_tf32(s[nf][0]), rnd_tf32(s[nf][1]));
                *(float2*)(prow1 + col) = make_float2(rnd_tf32(s[nf][2]), rnd_tf32(s[nf][3]));
            }
            __syncwarp();

            // ---- O += P @ V ----
#pragma unroll
            for (int kf = 0; kf < 8; kf++) {
                const int j = kf * 8;
                uint32_t pa[4];
                pa[0] = __float_as_uint(prow0[j + q]);
                pa[1] = __float_as_uint(prow1[j + q]);
                pa[2] = __float_as_uint(prow0[j + q + 4]);
                pa[3] = __float_as_uint(prow1[j + q + 4]);
#pragma unroll
                for (int nf = 0; nf < 8; nf++) {
                    const float* vr = vs + (j + q) * VSTR + nf * 8 + r;
                    uint32_t b0 = __float_as_uint(vr[0]);
                    uint32_t b1 = __float_as_uint(vr[4 * VSTR]);
                    mma_tf32(oc[nf], pa, b0, b1);
                }
            }
        }
        __syncthreads();
    }

    // ---- epilogue: normalize, tf32-round, write [B*S, D] ----
    const float inv0 = 1.f / l0;
    const float inv1 = 1.f / l1;
    float* o0 = out + (size_t)(b * PS + qbase + r) * PD + h * PDH;
    float* o1 = o0 + 8 * PD;
#pragma unroll
    for (int nf = 0; nf < 8; nf++) {
        const int col = nf * 8 + 2 * q;
        *(float2*)(o0 + col) = make_float2(rnd_tf32(oc[nf][0] * inv0),
                                           rnd_tf32(oc[nf][1] * inv0));
        *(float2*)(o1 + col) = make_float2(rnd_tf32(oc[nf][2] * inv1),
                                           rnd_tf32(oc[nf][3] * inv1));
    }
}

// ---------------------------------------------------------------------------
// kernel_launch
// ---------------------------------------------------------------------------
extern "C" void kernel_launch(void* const* d_in, const int* in_sizes, int n_in,
                              void* d_out, int out_size)
{
    const float* x     = (const float*)d_in[0];
    const float* W_qkv = (const float*)d_in[1];
    const float* b_qkv = (const float*)d_in[2];
    const float* W_out = (const float*)d_in[3];
    const float* b_out = (const float*)d_in[4];
    float* out = (float*)d_out;

    float *qkv, *attn, *xr, *wqr, *wor;
    cudaGetSymbolAddress((void**)&qkv,  g_qkv);
    cudaGetSymbolAddress((void**)&attn, g_attn);
    cudaGetSymbolAddress((void**)&xr,   g_xr);
    cudaGetSymbolAddress((void**)&wqr,  g_wqr);
    cudaGetSymbolAddress((void**)&wor,  g_wor);

    const int M = PB * PS;  // 8192
    const int gemm_smem = GEMM_SMEM_FLOATS * (int)sizeof(float);  // 107520
    const int fl_smem   = FL_SMEM_FLOATS * (int)sizeof(float);    // 106496

    static int configured = 0;
    if (!configured) {
        cudaFuncSetAttribute(tf32_gemm_bias<1>,
                             cudaFuncAttributeMaxDynamicSharedMemorySize, gemm_smem);
        cudaFuncSetAttribute(tf32_gemm_bias<0>,
                             cudaFuncAttributeMaxDynamicSharedMemorySize, gemm_smem);
        cudaFuncSetAttribute(flash_tc_kernel,
                             cudaFuncAttributeMaxDynamicSharedMemorySize, fl_smem);
        configured = 1;
    }

    // 0) pre-round inputs to tf32
    round_tf32_kernel<<<1024, 256>>>(x, xr, (PB * PS * PD) / 4);
    round_tf32_kernel<<<512, 256>>>(W_qkv, wqr, (PD * 3 * PD) / 4);
    round_tf32_kernel<<<256, 256>>>(W_out, wor, (PD * PD) / 4);

    // 1) QKV projection (output rounded to tf32 for flash)
    {
        dim3 grid(3 * PD / BN, M / BM);
        tf32_gemm_bias<1><<<grid, 256, gemm_smem>>>(xr, wqr, b_qkv, qkv, M, 3 * PD, PD);
    }

    // 2) Tensor-core flash attention (output rounded to tf32 for out-proj)
    {
        dim3 grid(PS / 128, PB * PH);
        flash_tc_kernel<<<grid, 256, fl_smem>>>(qkv, attn);
    }

    // 3) Output projection (full fp32 output)
    {
        dim3 grid(PD / BN, M / BM);
        tf32_gemm_bias<0><<<grid, 256, gemm_smem>>>(attn, wor, b_out, out, M, PD, PD);
    }
}

// round 6
// speedup vs baseline: 7.4883x; 1.8419x over previous
#include <cuda_runtime.h>
#include <cuda_fp16.h>
#include <math.h>
#include <cstdint>

// Problem constants: B=8, S=1024, D=1024, H=16, dh=64
#define PB 8
#define PS 1024
#define PD 1024
#define PH 16
#define PDH 64

// Scratch (allocation-free rule: __device__ globals)
__device__ __half g_qkvh[(size_t)PB * PS * 3 * PD];   // 48 MB [B*S, 3D] half
__device__ __half g_attnh[(size_t)PB * PS * PD];      // 16 MB [B*S, D] half
__device__ __half g_xh[(size_t)PB * PS * PD];         // 16 MB x half
__device__ __half g_wqh[(size_t)PD * 3 * PD];         //  6 MB W_qkv half [K,N]
__device__ __half g_woh[(size_t)PD * PD];             //  2 MB W_out half [K,N]

// ---------------------------------------------------------------------------
// Helpers
// ---------------------------------------------------------------------------
__device__ __forceinline__ void cpa16(void* dst, const void* src) {
    uint32_t d = (uint32_t)__cvta_generic_to_shared(dst);
    asm volatile("cp.async.cg.shared.global [%0], [%1], 16;\n" :: "r"(d), "l"(src));
}
__device__ __forceinline__ void mma_f16(float c[4], const uint32_t a[4],
                                        uint32_t b0, uint32_t b1) {
    asm volatile(
        "mma.sync.aligned.m16n8k16.row.col.f32.f16.f16.f32 "
        "{%0,%1,%2,%3}, {%4,%5,%6,%7}, {%8,%9}, {%0,%1,%2,%3};\n"
        : "+f"(c[0]), "+f"(c[1]), "+f"(c[2]), "+f"(c[3])
        : "r"(a[0]), "r"(a[1]), "r"(a[2]), "r"(a[3]), "r"(b0), "r"(b1));
}
__device__ __forceinline__ void ldsm_x4(uint32_t r[4], const __half* p) {
    uint32_t addr = (uint32_t)__cvta_generic_to_shared(p);
    asm volatile("ldmatrix.sync.aligned.m8n8.x4.shared.b16 {%0,%1,%2,%3}, [%4];\n"
                 : "=r"(r[0]), "=r"(r[1]), "=r"(r[2]), "=r"(r[3]) : "r"(addr));
}
__device__ __forceinline__ void ldsm_x4_t(uint32_t r[4], const __half* p) {
    uint32_t addr = (uint32_t)__cvta_generic_to_shared(p);
    asm volatile("ldmatrix.sync.aligned.m8n8.x4.trans.shared.b16 {%0,%1,%2,%3}, [%4];\n"
                 : "=r"(r[0]), "=r"(r[1]), "=r"(r[2]), "=r"(r[3]) : "r"(addr));
}
__device__ __forceinline__ uint32_t pack_h2(float lo, float hi) {
    __half2 h = __floats2half2_rn(lo, hi);
    return *(uint32_t*)&h;
}

// ---------------------------------------------------------------------------
// Prep: fp32 -> fp16 conversion (float4 grid-stride)
// ---------------------------------------------------------------------------
__global__ void f2h_kernel(const float* __restrict__ in,
                           __half* __restrict__ out, int n4)
{
    int i = blockIdx.x * blockDim.x + threadIdx.x;
    for (; i < n4; i += gridDim.x * blockDim.x) {
        float4 v = ((const float4*)in)[i];
        __half2 h0 = __floats2half2_rn(v.x, v.y);
        __half2 h1 = __floats2half2_rn(v.z, v.w);
        ((__half2*)out)[2 * i]     = h0;
        ((__half2*)out)[2 * i + 1] = h1;
    }
}

// ---------------------------------------------------------------------------
// FP16 tensor-core GEMM with bias: C[M,N] = A[M,K] @ B[K,N] + bias[N]
// A half [M,K] row-major; B half [K,N] row-major (ldmatrix.trans for frags).
// 256 threads = 8 warps (2m x 4n), block tile 128x128, BK=32, warp 64x32.
// OUTH=1 -> store half; OUTH=0 -> store fp32. 3-stage cp.async pipeline.
// ---------------------------------------------------------------------------
#define HBM 128
#define HBN 128
#define HBK 32
#define NSTAGE 3
#define HASTR 40     // halves (80B rows -> conflict-free ldmatrix)
#define HBSTR 136    // halves (272B rows -> conflict-free ldmatrix.trans)
#define HSTAGE_HALves (HBM * HASTR + HBK * HBSTR)
#define HGEMM_SMEM (NSTAGE * HSTAGE_HALves * 2)   // bytes = 3*18944 = 56832

template<int OUTH>
__global__ __launch_bounds__(256, 2) void f16_gemm_bias(
    const __half* __restrict__ A, const __half* __restrict__ Bm,
    const float* __restrict__ bias, void* __restrict__ Cv,
    int M, int N, int K)
{
    extern __shared__ __half smh[];

    const int t    = threadIdx.x;
    const int w    = t >> 5;
    const int lane = t & 31;
    const int bm   = blockIdx.y * HBM;
    const int bn   = blockIdx.x * HBN;
    const int wm   = (w & 1) * 64;
    const int wn   = (w >> 1) * 32;
    const int r    = lane >> 2;
    const int q    = lane & 3;

    const int KT = K / HBK;

    auto stage = [&](int s, int buf) {
        __half* sa = smh + buf * HSTAGE_HALves;
        __half* sb = sa + HBM * HASTR;
        const __half* ga = A + (size_t)bm * K + s * HBK;
#pragma unroll
        for (int i = 0; i < 2; i++) {
            const int ch = t + i * 256;           // 0..511
            const int row = ch >> 2, c8 = (ch & 3) * 8;
            cpa16(sa + row * HASTR + c8, ga + (size_t)row * K + c8);
        }
        const __half* gb = Bm + (size_t)(s * HBK) * N + bn;
#pragma unroll
        for (int i = 0; i < 2; i++) {
            const int ch = t + i * 256;           // 0..511
            const int row = ch >> 4, c8 = (ch & 15) * 8;
            cpa16(sb + row * HBSTR + c8, gb + (size_t)row * N + c8);
        }
    };

    float c[4][4][4];
#pragma unroll
    for (int mf = 0; mf < 4; mf++)
#pragma unroll
        for (int nf = 0; nf < 4; nf++)
#pragma unroll
            for (int i = 0; i < 4; i++) c[mf][nf][i] = 0.f;

    stage(0, 0);
    asm volatile("cp.async.commit_group;\n");
    stage(1, 1);
    asm volatile("cp.async.commit_group;\n");

    // ldmatrix lane-address constants
    const int a_row = lane & 15;                  // row within 16-row block
    const int a_kof = (lane & 16) ? 8 : 0;        // k lo/hi 8
    const int b_krow = lane & 15;                 // k row within 16
    const int b_nof  = (lane & 16) ? 8 : 0;       // n lo/hi 8

    for (int s = 0; s < KT; s++) {
        const int buf = s % NSTAGE;
        if (s + 1 < KT) asm volatile("cp.async.wait_group 1;\n");
        else            asm volatile("cp.async.wait_group 0;\n");
        __syncthreads();
        if (s + 2 < KT) {
            stage(s + 2, (s + 2) % NSTAGE);
            asm volatile("cp.async.commit_group;\n");
        }

        const __half* sa = smh + buf * HSTAGE_HALves;
        const __half* sb = sa + HBM * HASTR;

#pragma unroll
        for (int kb = 0; kb < 2; kb++) {
            const int k0 = kb * 16;
            uint32_t a[4][4];
#pragma unroll
            for (int mf = 0; mf < 4; mf++)
                ldsm_x4(a[mf], sa + (wm + mf * 16 + a_row) * HASTR + k0 + a_kof);

            uint32_t bf[2][4];
#pragma unroll
            for (int ng = 0; ng < 2; ng++)
                ldsm_x4_t(bf[ng], sb + (k0 + b_krow) * HBSTR + wn + ng * 16 + b_nof);

#pragma unroll
            for (int ng = 0; ng < 2; ng++)
#pragma unroll
                for (int sub = 0; sub < 2; sub++) {
                    const int nf = ng * 2 + sub;
                    const uint32_t b0 = bf[ng][2 * sub], b1 = bf[ng][2 * sub + 1];
#pragma unroll
                    for (int mf = 0; mf < 4; mf++)
                        mma_f16(c[mf][nf], a[mf], b0, b1);
                }
        }
    }

    // epilogue with fp32 bias
#pragma unroll
    for (int mf = 0; mf < 4; mf++) {
        const int row0 = bm + wm + mf * 16 + r;
#pragma unroll
        for (int nf = 0; nf < 4; nf++) {
            const int col = bn + wn + nf * 8 + q * 2;
            float2 bi = *(const float2*)(bias + col);
            const float v00 = c[mf][nf][0] + bi.x, v01 = c[mf][nf][1] + bi.y;
            const float v10 = c[mf][nf][2] + bi.x, v11 = c[mf][nf][3] + bi.y;
            if (OUTH) {
                __half* C = (__half*)Cv;
                *(__half2*)(C + (size_t)row0 * N + col)       = __floats2half2_rn(v00, v01);
                *(__half2*)(C + (size_t)(row0 + 8) * N + col) = __floats2half2_rn(v10, v11);
            } else {
                float* C = (float*)Cv;
                *(float2*)(C + (size_t)row0 * N + col)       = make_float2(v00, v01);
                *(float2*)(C + (size_t)(row0 + 8) * N + col) = make_float2(v10, v11);
            }
        }
    }
}

// ---------------------------------------------------------------------------
// FP16 tensor-core flash attention (fp32 accum, causal).
// qkv half [B*S, 3072]. Q frags from gmem (scaled 0.125). K/V smem,
// double-buffered cp.async. S frag reused directly as P A-frag (no smem P).
// Grid (8 qtiles, 128 b*h). Block 256 = 8 warps; warp owns 16 q rows.
// smem: K[2][64][72] + V[2][64][72] halves = 36864 B.
// ---------------------------------------------------------------------------
#define FKSTR 72
#define FL_SMEM (2 * 64 * FKSTR * 2 * 2)   // bytes

__global__ __launch_bounds__(256) void flash_f16_kernel(
    const __half* __restrict__ qkv, __half* __restrict__ out)
{
    extern __shared__ __half smf[];
    __half* Ks = smf;                    // [2][64][FKSTR]
    __half* Vs = smf + 2 * 64 * FKSTR;   // [2][64][FKSTR]

    const int t    = threadIdx.x;
    const int w    = t >> 5;
    const int lane = t & 31;
    const int r    = lane >> 2;
    const int q    = lane & 3;
    const int qt   = blockIdx.x;
    const int bh   = blockIdx.y;
    const int b    = bh / PH;
    const int h    = bh % PH;

    const int qbase = qt * 128 + w * 16;
    const int RS = 3 * PD;  // 3072

    const __half* kbase = qkv + (size_t)(b * PS) * RS + PD + h * PDH;
    const __half* vbase = kbase + PD;

    // ---- Q fragments from gmem, scaled by 0.125 (exact pow2) ----
    uint32_t qa[4][4];
    {
        const __half* qp = qkv + (size_t)(b * PS + qbase) * RS + h * PDH;
        const __half2 scl = __float2half2_rn(0.125f);
#pragma unroll
        for (int kb = 0; kb < 4; kb++) {
            const int c0 = kb * 16 + 2 * q;
            uint32_t raw[4];
            raw[0] = *(const uint32_t*)(qp + (size_t)r * RS + c0);
            raw[1] = *(const uint32_t*)(qp + (size_t)(r + 8) * RS + c0);
            raw[2] = *(const uint32_t*)(qp + (size_t)r * RS + c0 + 8);
            raw[3] = *(const uint32_t*)(qp + (size_t)(r + 8) * RS + c0 + 8);
#pragma unroll
            for (int i = 0; i < 4; i++) {
                __half2 hh = __hmul2(*(__half2*)&raw[i], scl);
                qa[kb][i] = *(uint32_t*)&hh;
            }
        }
    }

    float oc[8][4];
#pragma unroll
    for (int nf = 0; nf < 8; nf++)
#pragma unroll
        for (int i = 0; i < 4; i++) oc[nf][i] = 0.f;
    float m0 = -1e30f, m1 = -1e30f, l0 = 0.f, l1 = 0.f;

    const int nkt = 2 * qt + 2;

    auto stage = [&](int kt, int buf) {
        __half* ks = Ks + buf * 64 * FKSTR;
        __half* vs = Vs + buf * 64 * FKSTR;
#pragma unroll
        for (int i = 0; i < 2; i++) {
            const int ch = t + i * 256;           // 0..511
            const int row = ch >> 3, c8 = (ch & 7) * 8;
            const size_t go = (size_t)(kt * 64 + row) * RS + c8;
            cpa16(ks + row * FKSTR + c8, kbase + go);
            cpa16(vs + row * FKSTR + c8, vbase + go);
        }
    };

    stage(0, 0);
    asm volatile("cp.async.commit_group;\n");

    // ldmatrix lane constants
    const int kj_of = (lane & 7) + ((lane & 16) ? 8 : 0);  // K (non-trans) j row
    const int kk_of = (lane & 8) ? 8 : 0;                  // K k lo/hi
    const int vj_of = lane & 15;                           // V (trans) j row
    const int vd_of = (lane & 16) ? 8 : 0;                 // V d lo/hi

    for (int kt = 0; kt < nkt; kt++) {
        const int buf = kt & 1;
        if (kt + 1 < nkt) {
            stage(kt + 1, buf ^ 1);
            asm volatile("cp.async.commit_group;\n");
            asm volatile("cp.async.wait_group 1;\n");
        } else {
            asm volatile("cp.async.wait_group 0;\n");
        }
        __syncthreads();

        const int gk0 = kt * 64;
        if (gk0 <= qbase + 15) {
            const __half* ks = Ks + buf * 64 * FKSTR;
            const __half* vs = Vs + buf * 64 * FKSTR;

            // ---- S = Q @ K^T ----
            float s[8][4];
#pragma unroll
            for (int nf = 0; nf < 8; nf++)
#pragma unroll
                for (int i = 0; i < 4; i++) s[nf][i] = 0.f;

#pragma unroll
            for (int kb = 0; kb < 4; kb++) {
                const int k0 = kb * 16;
#pragma unroll
                for (int jg = 0; jg < 4; jg++) {
                    uint32_t kb4[4];
                    ldsm_x4(kb4, ks + (jg * 16 + kj_of) * FKSTR + k0 + kk_of);
                    mma_f16(s[2 * jg],     qa[kb], kb4[0], kb4[1]);
                    mma_f16(s[2 * jg + 1], qa[kb], kb4[2], kb4[3]);
                }
            }

            // ---- causal mask ----
            if (gk0 + 63 > qbase) {
                const int gq0 = qbase + r;
                const int gq1 = gq0 + 8;
#pragma unroll
                for (int nf = 0; nf < 8; nf++) {
                    const int gk = gk0 + nf * 8 + 2 * q;
                    if (gk > gq0)     s[nf][0] = -1e30f;
                    if (gk + 1 > gq0) s[nf][1] = -1e30f;
                    if (gk > gq1)     s[nf][2] = -1e30f;
                    if (gk + 1 > gq1) s[nf][3] = -1e30f;
                }
            }

            // ---- online softmax ----
            float rm0 = s[0][0], rm1 = s[0][2];
#pragma unroll
            for (int nf = 0; nf < 8; nf++) {
                rm0 = fmaxf(rm0, fmaxf(s[nf][0], s[nf][1]));
                rm1 = fmaxf(rm1, fmaxf(s[nf][2], s[nf][3]));
            }
            rm0 = fmaxf(rm0, __shfl_xor_sync(0xffffffffu, rm0, 1));
            rm0 = fmaxf(rm0, __shfl_xor_sync(0xffffffffu, rm0, 2));
            rm1 = fmaxf(rm1, __shfl_xor_sync(0xffffffffu, rm1, 1));
            rm1 = fmaxf(rm1, __shfl_xor_sync(0xffffffffu, rm1, 2));
            const float mn0 = fmaxf(m0, rm0);
            const float mn1 = fmaxf(m1, rm1);
            const float corr0 = __expf(m0 - mn0);
            const float corr1 = __expf(m1 - mn1);
            float rs0 = 0.f, rs1 = 0.f;
#pragma unroll
            for (int nf = 0; nf < 8; nf++) {
                s[nf][0] = __expf(s[nf][0] - mn0);
                s[nf][1] = __expf(s[nf][1] - mn0);
                s[nf][2] = __expf(s[nf][2] - mn1);
                s[nf][3] = __expf(s[nf][3] - mn1);
                rs0 += s[nf][0] + s[nf][1];
                rs1 += s[nf][2] + s[nf][3];
            }
            rs0 += __shfl_xor_sync(0xffffffffu, rs0, 1);
            rs0 += __shfl_xor_sync(0xffffffffu, rs0, 2);
            rs1 += __shfl_xor_sync(0xffffffffu, rs1, 1);
            rs1 += __shfl_xor_sync(0xffffffffu, rs1, 2);
            l0 = l0 * corr0 + rs0;  m0 = mn0;
            l1 = l1 * corr1 + rs1;  m1 = mn1;
#pragma unroll
            for (int nf = 0; nf < 8; nf++) {
                oc[nf][0] *= corr0; oc[nf][1] *= corr0;
                oc[nf][2] *= corr1; oc[nf][3] *= corr1;
            }

            // ---- pack P into A fragments (register-only) ----
            uint32_t pa[4][4];
#pragma unroll
            for (int jb = 0; jb < 4; jb++) {
                pa[jb][0] = pack_h2(s[2 * jb][0],     s[2 * jb][1]);
                pa[jb][1] = pack_h2(s[2 * jb][2],     s[2 * jb][3]);
                pa[jb][2] = pack_h2(s[2 * jb + 1][0], s[2 * jb + 1][1]);
                pa[jb][3] = pack_h2(s[2 * jb + 1][2], s[2 * jb + 1][3]);
            }

            // ---- O += P @ V ----
#pragma unroll
            for (int jb = 0; jb < 4; jb++) {
#pragma unroll
                for (int dg = 0; dg < 4; dg++) {
                    uint32_t vb4[4];
                    ldsm_x4_t(vb4, vs + (jb * 16 + vj_of) * FKSTR + dg * 16 + vd_of);
                    mma_f16(oc[2 * dg],     pa[jb], vb4[0], vb4[1]);
                    mma_f16(oc[2 * dg + 1], pa[jb], vb4[2], vb4[3]);
                }
            }
        }
        __syncthreads();
    }

    // ---- epilogue: normalize, store half [B*S, D] ----
    const float inv0 = 1.f / l0;
    const float inv1 = 1.f / l1;
    __half* o0 = out + (size_t)(b * PS + qbase + r) * PD + h * PDH;
    __half* o1 = o0 + (size_t)8 * PD;
#pragma unroll
    for (int nf = 0; nf < 8; nf++) {
        const int col = nf * 8 + 2 * q;
        *(__half2*)(o0 + col) = __floats2half2_rn(oc[nf][0] * inv0, oc[nf][1] * inv0);
        *(__half2*)(o1 + col) = __floats2half2_rn(oc[nf][2] * inv1, oc[nf][3] * inv1);
    }
}

// ---------------------------------------------------------------------------
// kernel_launch
// ---------------------------------------------------------------------------
extern "C" void kernel_launch(void* const* d_in, const int* in_sizes, int n_in,
                              void* d_out, int out_size)
{
    const float* x     = (const float*)d_in[0];
    const float* W_qkv = (const float*)d_in[1];
    const float* b_qkv = (const float*)d_in[2];
    const float* W_out = (const float*)d_in[3];
    const float* b_out = (const float*)d_in[4];
    float* out = (float*)d_out;

    __half *qkvh, *attnh, *xh, *wqh, *woh;
    cudaGetSymbolAddress((void**)&qkvh,  g_qkvh);
    cudaGetSymbolAddress((void**)&attnh, g_attnh);
    cudaGetSymbolAddress((void**)&xh,    g_xh);
    cudaGetSymbolAddress((void**)&wqh,   g_wqh);
    cudaGetSymbolAddress((void**)&woh,   g_woh);

    const int M = PB * PS;  // 8192

    static int configured = 0;
    if (!configured) {
        cudaFuncSetAttribute(f16_gemm_bias<1>,
                             cudaFuncAttributeMaxDynamicSharedMemorySize, HGEMM_SMEM);
        cudaFuncSetAttribute(f16_gemm_bias<0>,
                             cudaFuncAttributeMaxDynamicSharedMemorySize, HGEMM_SMEM);
        configured = 1;
    }

    // 0) prep: fp32 -> fp16 conversions
    f2h_kernel<<<1024, 256>>>(x, xh, (PB * PS * PD) / 4);
    f2h_kernel<<<512, 256>>>(W_qkv, wqh, (PD * 3 * PD) / 4);
    f2h_kernel<<<256, 256>>>(W_out, woh, (PD * PD) / 4);

    // 1) QKV projection: [8192,1024] @ [1024,3072] + b -> half
    {
        dim3 grid(3 * PD / HBN, M / HBM);  // (24, 64)
        f16_gemm_bias<1><<<grid, 256, HGEMM_SMEM>>>(xh, wqh, b_qkv, qkvh,
                                                    M, 3 * PD, PD);
    }

    // 2) FP16 flash attention -> half
    {
        dim3 grid(PS / 128, PB * PH);
        flash_f16_kernel<<<grid, 256, FL_SMEM>>>(qkvh, attnh);
    }

    // 3) Output projection: [8192,1024] @ [1024,1024] + b -> fp32
    {
        dim3 grid(PD / HBN, M / HBM);  // (8, 64)
        f16_gemm_bias<0><<<grid, 256, HGEMM_SMEM>>>(attnh, woh, b_out, out,
                                                    M, PD, PD);
    }
}

// round 7
// speedup vs baseline: 7.6923x; 1.0272x over previous
#include <cuda_runtime.h>
#include <cuda_fp16.h>
#include <math.h>
#include <cstdint>

// Problem constants: B=8, S=1024, D=1024, H=16, dh=64
#define PB 8
#define PS 1024
#define PD 1024
#define PH 16
#define PDH 64

// Scratch (allocation-free rule: __device__ globals)
__device__ __half g_qkvh[(size_t)PB * PS * 3 * PD];   // 48 MB [B*S, 3D] half
__device__ __half g_attnh[(size_t)PB * PS * PD];      // 16 MB [B*S, D] half
__device__ __half g_xh[(size_t)PB * PS * PD];         // 16 MB x half
__device__ __half g_wqh[(size_t)PD * 3 * PD];         //  6 MB W_qkv half [K,N]
__device__ __half g_woh[(size_t)PD * PD];             //  2 MB W_out half [K,N]

// ---------------------------------------------------------------------------
// Helpers
// ---------------------------------------------------------------------------
__device__ __forceinline__ void cpa16(void* dst, const void* src) {
    uint32_t d = (uint32_t)__cvta_generic_to_shared(dst);
    asm volatile("cp.async.cg.shared.global [%0], [%1], 16;\n" :: "r"(d), "l"(src));
}
__device__ __forceinline__ void mma_f16(float c[4], const uint32_t a[4],
                                        uint32_t b0, uint32_t b1) {
    asm volatile(
        "mma.sync.aligned.m16n8k16.row.col.f32.f16.f16.f32 "
        "{%0,%1,%2,%3}, {%4,%5,%6,%7}, {%8,%9}, {%0,%1,%2,%3};\n"
        : "+f"(c[0]), "+f"(c[1]), "+f"(c[2]), "+f"(c[3])
        : "r"(a[0]), "r"(a[1]), "r"(a[2]), "r"(a[3]), "r"(b0), "r"(b1));
}
__device__ __forceinline__ void ldsm_x4(uint32_t r[4], const __half* p) {
    uint32_t addr = (uint32_t)__cvta_generic_to_shared(p);
    asm volatile("ldmatrix.sync.aligned.m8n8.x4.shared.b16 {%0,%1,%2,%3}, [%4];\n"
                 : "=r"(r[0]), "=r"(r[1]), "=r"(r[2]), "=r"(r[3]) : "r"(addr));
}
__device__ __forceinline__ void ldsm_x4_t(uint32_t r[4], const __half* p) {
    uint32_t addr = (uint32_t)__cvta_generic_to_shared(p);
    asm volatile("ldmatrix.sync.aligned.m8n8.x4.trans.shared.b16 {%0,%1,%2,%3}, [%4];\n"
                 : "=r"(r[0]), "=r"(r[1]), "=r"(r[2]), "=r"(r[3]) : "r"(addr));
}
__device__ __forceinline__ uint32_t pack_h2(float lo, float hi) {
    __half2 h = __floats2half2_rn(lo, hi);
    return *(uint32_t*)&h;
}

// ---------------------------------------------------------------------------
// Prep: fp32 -> fp16 conversion (float4 grid-stride)
// ---------------------------------------------------------------------------
__global__ void f2h_kernel(const float* __restrict__ in,
                           __half* __restrict__ out, int n4)
{
    int i = blockIdx.x * blockDim.x + threadIdx.x;
    for (; i < n4; i += gridDim.x * blockDim.x) {
        float4 v = ((const float4*)in)[i];
        __half2 h0 = __floats2half2_rn(v.x, v.y);
        __half2 h1 = __floats2half2_rn(v.z, v.w);
        ((__half2*)out)[2 * i]     = h0;
        ((__half2*)out)[2 * i + 1] = h1;
    }
}

// ---------------------------------------------------------------------------
// FP16 tensor-core GEMM with bias: C[M,N] = A[M,K] @ B[K,N] + bias[N]
// A half [M,K] row-major; B half [K,N] row-major (ldmatrix.trans fragments).
// 128 threads = 4 warps (2m x 2n), block tile 128x128, BK=32, warp 64x64.
// 32 mma per 8 ldsm per warp per k16 -> smem traffic no longer co-binding.
// OUTH=1 -> store half; OUTH=0 -> store fp32. 3-stage cp.async pipeline.
// ---------------------------------------------------------------------------
#define HBM 128
#define HBN 128
#define HBK 32
#define NSTAGE 3
#define HASTR 40     // halves (80B rows -> conflict-free ldmatrix)
#define HBSTR 136    // halves (272B rows -> conflict-free ldmatrix.trans)
#define HSTAGE_H (HBM * HASTR + HBK * HBSTR)      // 9472 halves
#define HGEMM_SMEM (NSTAGE * HSTAGE_H * 2)        // 56832 bytes

template<int OUTH>
__global__ __launch_bounds__(128) void f16_gemm_bias(
    const __half* __restrict__ A, const __half* __restrict__ Bm,
    const float* __restrict__ bias, void* __restrict__ Cv,
    int M, int N, int K)
{
    extern __shared__ __half smh[];

    const int t    = threadIdx.x;
    const int w    = t >> 5;
    const int lane = t & 31;
    const int bm   = blockIdx.y * HBM;
    const int bn   = blockIdx.x * HBN;
    const int wm   = (w & 1) * 64;
    const int wn   = (w >> 1) * 64;
    const int r    = lane >> 2;
    const int q    = lane & 3;

    const int KT = K / HBK;

    auto stage = [&](int s, int buf) {
        __half* sa = smh + buf * HSTAGE_H;
        __half* sb = sa + HBM * HASTR;
        const __half* ga = A + (size_t)bm * K + s * HBK;
#pragma unroll
        for (int i = 0; i < 4; i++) {
            const int ch = t + i * 128;           // 0..511
            const int row = ch >> 2, c8 = (ch & 3) * 8;
            cpa16(sa + row * HASTR + c8, ga + (size_t)row * K + c8);
        }
        const __half* gb = Bm + (size_t)(s * HBK) * N + bn;
#pragma unroll
        for (int i = 0; i < 4; i++) {
            const int ch = t + i * 128;           // 0..511
            const int row = ch >> 4, c8 = (ch & 15) * 8;
            cpa16(sb + row * HBSTR + c8, gb + (size_t)row * N + c8);
        }
    };

    float c[4][8][4];
#pragma unroll
    for (int mf = 0; mf < 4; mf++)
#pragma unroll
        for (int nf = 0; nf < 8; nf++)
#pragma unroll
            for (int i = 0; i < 4; i++) c[mf][nf][i] = 0.f;

    stage(0, 0);
    asm volatile("cp.async.commit_group;\n");
    stage(1, 1);
    asm volatile("cp.async.commit_group;\n");

    // ldmatrix lane-address constants
    const int a_row  = lane & 15;                 // row within 16-row block
    const int a_kof  = (lane & 16) ? 8 : 0;       // k lo/hi 8
    const int b_krow = lane & 15;                 // k row within 16
    const int b_nof  = (lane & 16) ? 8 : 0;       // n lo/hi 8

    for (int s = 0; s < KT; s++) {
        const int buf = s % NSTAGE;
        if (s + 1 < KT) asm volatile("cp.async.wait_group 1;\n");
        else            asm volatile("cp.async.wait_group 0;\n");
        __syncthreads();
        if (s + 2 < KT) {
            stage(s + 2, (s + 2) % NSTAGE);
            asm volatile("cp.async.commit_group;\n");
        }

        const __half* sa = smh + buf * HSTAGE_H;
        const __half* sb = sa + HBM * HASTR;

#pragma unroll
        for (int kb = 0; kb < 2; kb++) {
            const int k0 = kb * 16;
            uint32_t a[4][4];
#pragma unroll
            for (int mf = 0; mf < 4; mf++)
                ldsm_x4(a[mf], sa + (wm + mf * 16 + a_row) * HASTR + k0 + a_kof);

            uint32_t bf[4][4];
#pragma unroll
            for (int ng = 0; ng < 4; ng++)
                ldsm_x4_t(bf[ng], sb + (k0 + b_krow) * HBSTR + wn + ng * 16 + b_nof);

#pragma unroll
            for (int ng = 0; ng < 4; ng++)
#pragma unroll
                for (int sub = 0; sub < 2; sub++) {
                    const int nf = ng * 2 + sub;
                    const uint32_t b0 = bf[ng][2 * sub], b1 = bf[ng][2 * sub + 1];
#pragma unroll
                    for (int mf = 0; mf < 4; mf++)
                        mma_f16(c[mf][nf], a[mf], b0, b1);
                }
        }
    }

    // epilogue with fp32 bias
#pragma unroll
    for (int mf = 0; mf < 4; mf++) {
        const int row0 = bm + wm + mf * 16 + r;
#pragma unroll
        for (int nf = 0; nf < 8; nf++) {
            const int col = bn + wn + nf * 8 + q * 2;
            float2 bi = *(const float2*)(bias + col);
            const float v00 = c[mf][nf][0] + bi.x, v01 = c[mf][nf][1] + bi.y;
            const float v10 = c[mf][nf][2] + bi.x, v11 = c[mf][nf][3] + bi.y;
            if (OUTH) {
                __half* C = (__half*)Cv;
                *(__half2*)(C + (size_t)row0 * N + col)       = __floats2half2_rn(v00, v01);
                *(__half2*)(C + (size_t)(row0 + 8) * N + col) = __floats2half2_rn(v10, v11);
            } else {
                float* C = (float*)Cv;
                *(float2*)(C + (size_t)row0 * N + col)       = make_float2(v00, v01);
                *(float2*)(C + (size_t)(row0 + 8) * N + col) = make_float2(v10, v11);
            }
        }
    }
}

// ---------------------------------------------------------------------------
// FP16 tensor-core flash attention (fp32 accum, causal) — unchanged.
// ---------------------------------------------------------------------------
#define FKSTR 72
#define FL_SMEM (2 * 64 * FKSTR * 2 * 2)   // bytes

__global__ __launch_bounds__(256) void flash_f16_kernel(
    const __half* __restrict__ qkv, __half* __restrict__ out)
{
    extern __shared__ __half smf[];
    __half* Ks = smf;                    // [2][64][FKSTR]
    __half* Vs = smf + 2 * 64 * FKSTR;   // [2][64][FKSTR]

    const int t    = threadIdx.x;
    const int w    = t >> 5;
    const int lane = t & 31;
    const int r    = lane >> 2;
    const int q    = lane & 3;
    const int qt   = blockIdx.x;
    const int bh   = blockIdx.y;
    const int b    = bh / PH;
    const int h    = bh % PH;

    const int qbase = qt * 128 + w * 16;
    const int RS = 3 * PD;  // 3072

    const __half* kbase = qkv + (size_t)(b * PS) * RS + PD + h * PDH;
    const __half* vbase = kbase + PD;

    // ---- Q fragments from gmem, scaled by 0.125 (exact pow2) ----
    uint32_t qa[4][4];
    {
        const __half* qp = qkv + (size_t)(b * PS + qbase) * RS + h * PDH;
        const __half2 scl = __float2half2_rn(0.125f);
#pragma unroll
        for (int kb = 0; kb < 4; kb++) {
            const int c0 = kb * 16 + 2 * q;
            uint32_t raw[4];
            raw[0] = *(const uint32_t*)(qp + (size_t)r * RS + c0);
            raw[1] = *(const uint32_t*)(qp + (size_t)(r + 8) * RS + c0);
            raw[2] = *(const uint32_t*)(qp + (size_t)r * RS + c0 + 8);
            raw[3] = *(const uint32_t*)(qp + (size_t)(r + 8) * RS + c0 + 8);
#pragma unroll
            for (int i = 0; i < 4; i++) {
                __half2 hh = __hmul2(*(__half2*)&raw[i], scl);
                qa[kb][i] = *(uint32_t*)&hh;
            }
        }
    }

    float oc[8][4];
#pragma unroll
    for (int nf = 0; nf < 8; nf++)
#pragma unroll
        for (int i = 0; i < 4; i++) oc[nf][i] = 0.f;
    float m0 = -1e30f, m1 = -1e30f, l0 = 0.f, l1 = 0.f;

    const int nkt = 2 * qt + 2;

    auto stage = [&](int kt, int buf) {
        __half* ks = Ks + buf * 64 * FKSTR;
        __half* vs = Vs + buf * 64 * FKSTR;
#pragma unroll
        for (int i = 0; i < 2; i++) {
            const int ch = t + i * 256;           // 0..511
            const int row = ch >> 3, c8 = (ch & 7) * 8;
            const size_t go = (size_t)(kt * 64 + row) * RS + c8;
            cpa16(ks + row * FKSTR + c8, kbase + go);
            cpa16(vs + row * FKSTR + c8, vbase + go);
        }
    };

    stage(0, 0);
    asm volatile("cp.async.commit_group;\n");

    const int kj_of = (lane & 7) + ((lane & 16) ? 8 : 0);  // K (non-trans) j row
    const int kk_of = (lane & 8) ? 8 : 0;                  // K k lo/hi
    const int vj_of = lane & 15;                           // V (trans) j row
    const int vd_of = (lane & 16) ? 8 : 0;                 // V d lo/hi

    for (int kt = 0; kt < nkt; kt++) {
        const int buf = kt & 1;
        if (kt + 1 < nkt) {
            stage(kt + 1, buf ^ 1);
            asm volatile("cp.async.commit_group;\n");
            asm volatile("cp.async.wait_group 1;\n");
        } else {
            asm volatile("cp.async.wait_group 0;\n");
        }
        __syncthreads();

        const int gk0 = kt * 64;
        if (gk0 <= qbase + 15) {
            const __half* ks = Ks + buf * 64 * FKSTR;
            const __half* vs = Vs + buf * 64 * FKSTR;

            // ---- S = Q @ K^T ----
            float s[8][4];
#pragma unroll
            for (int nf = 0; nf < 8; nf++)
#pragma unroll
                for (int i = 0; i < 4; i++) s[nf][i] = 0.f;

#pragma unroll
            for (int kb = 0; kb < 4; kb++) {
                const int k0 = kb * 16;
#pragma unroll
                for (int jg = 0; jg < 4; jg++) {
                    uint32_t kb4[4];
                    ldsm_x4(kb4, ks + (jg * 16 + kj_of) * FKSTR + k0 + kk_of);
                    mma_f16(s[2 * jg],     qa[kb], kb4[0], kb4[1]);
                    mma_f16(s[2 * jg + 1], qa[kb], kb4[2], kb4[3]);
                }
            }

            // ---- causal mask ----
            if (gk0 + 63 > qbase) {
                const int gq0 = qbase + r;
                const int gq1 = gq0 + 8;
#pragma unroll
                for (int nf = 0; nf < 8; nf++) {
                    const int gk = gk0 + nf * 8 + 2 * q;
                    if (gk > gq0)     s[nf][0] = -1e30f;
                    if (gk + 1 > gq0) s[nf][1] = -1e30f;
                    if (gk > gq1)     s[nf][2] = -1e30f;
                    if (gk + 1 > gq1) s[nf][3] = -1e30f;
                }
            }

            // ---- online softmax ----
            float rm0 = s[0][0], rm1 = s[0][2];
#pragma unroll
            for (int nf = 0; nf < 8; nf++) {
                rm0 = fmaxf(rm0, fmaxf(s[nf][0], s[nf][1]));
                rm1 = fmaxf(rm1, fmaxf(s[nf][2], s[nf][3]));
            }
            rm0 = fmaxf(rm0, __shfl_xor_sync(0xffffffffu, rm0, 1));
            rm0 = fmaxf(rm0, __shfl_xor_sync(0xffffffffu, rm0, 2));
            rm1 = fmaxf(rm1, __shfl_xor_sync(0xffffffffu, rm1, 1));
            rm1 = fmaxf(rm1, __shfl_xor_sync(0xffffffffu, rm1, 2));
            const float mn0 = fmaxf(m0, rm0);
            const float mn1 = fmaxf(m1, rm1);
            const float corr0 = __expf(m0 - mn0);
            const float corr1 = __expf(m1 - mn1);
            float rs0 = 0.f, rs1 = 0.f;
#pragma unroll
            for (int nf = 0; nf < 8; nf++) {
                s[nf][0] = __expf(s[nf][0] - mn0);
                s[nf][1] = __expf(s[nf][1] - mn0);
                s[nf][2] = __expf(s[nf][2] - mn1);
                s[nf][3] = __expf(s[nf][3] - mn1);
                rs0 += s[nf][0] + s[nf][1];
                rs1 += s[nf][2] + s[nf][3];
            }
            rs0 += __shfl_xor_sync(0xffffffffu, rs0, 1);
            rs0 += __shfl_xor_sync(0xffffffffu, rs0, 2);
            rs1 += __shfl_xor_sync(0xffffffffu, rs1, 1);
            rs1 += __shfl_xor_sync(0xffffffffu, rs1, 2);
            l0 = l0 * corr0 + rs0;  m0 = mn0;
            l1 = l1 * corr1 + rs1;  m1 = mn1;
#pragma unroll
            for (int nf = 0; nf < 8; nf++) {
                oc[nf][0] *= corr0; oc[nf][1] *= corr0;
                oc[nf][2] *= corr1; oc[nf][3] *= corr1;
            }

            // ---- pack P into A fragments (register-only) ----
            uint32_t pa[4][4];
#pragma unroll
            for (int jb = 0; jb < 4; jb++) {
                pa[jb][0] = pack_h2(s[2 * jb][0],     s[2 * jb][1]);
                pa[jb][1] = pack_h2(s[2 * jb][2],     s[2 * jb][3]);
                pa[jb][2] = pack_h2(s[2 * jb + 1][0], s[2 * jb + 1][1]);
                pa[jb][3] = pack_h2(s[2 * jb + 1][2], s[2 * jb + 1][3]);
            }

            // ---- O += P @ V ----
#pragma unroll
            for (int jb = 0; jb < 4; jb++) {
#pragma unroll
                for (int dg = 0; dg < 4; dg++) {
                    uint32_t vb4[4];
                    ldsm_x4_t(vb4, vs + (jb * 16 + vj_of) * FKSTR + dg * 16 + vd_of);
                    mma_f16(oc[2 * dg],     pa[jb], vb4[0], vb4[1]);
                    mma_f16(oc[2 * dg + 1], pa[jb], vb4[2], vb4[3]);
                }
            }
        }
        __syncthreads();
    }

    // ---- epilogue: normalize, store half [B*S, D] ----
    const float inv0 = 1.f / l0;
    const float inv1 = 1.f / l1;
    __half* o0 = out + (size_t)(b * PS + qbase + r) * PD + h * PDH;
    __half* o1 = o0 + (size_t)8 * PD;
#pragma unroll
    for (int nf = 0; nf < 8; nf++) {
        const int col = nf * 8 + 2 * q;
        *(__half2*)(o0 + col) = __floats2half2_rn(oc[nf][0] * inv0, oc[nf][1] * inv0);
        *(__half2*)(o1 + col) = __floats2half2_rn(oc[nf][2] * inv1, oc[nf][3] * inv1);
    }
}

// ---------------------------------------------------------------------------
// kernel_launch
// ---------------------------------------------------------------------------
extern "C" void kernel_launch(void* const* d_in, const int* in_sizes, int n_in,
                              void* d_out, int out_size)
{
    const float* x     = (const float*)d_in[0];
    const float* W_qkv = (const float*)d_in[1];
    const float* b_qkv = (const float*)d_in[2];
    const float* W_out = (const float*)d_in[3];
    const float* b_out = (const float*)d_in[4];
    float* out = (float*)d_out;

    __half *qkvh, *attnh, *xh, *wqh, *woh;
    cudaGetSymbolAddress((void**)&qkvh,  g_qkvh);
    cudaGetSymbolAddress((void**)&attnh, g_attnh);
    cudaGetSymbolAddress((void**)&xh,    g_xh);
    cudaGetSymbolAddress((void**)&wqh,   g_wqh);
    cudaGetSymbolAddress((void**)&woh,   g_woh);

    const int M = PB * PS;  // 8192

    static int configured = 0;
    if (!configured) {
        cudaFuncSetAttribute(f16_gemm_bias<1>,
                             cudaFuncAttributeMaxDynamicSharedMemorySize, HGEMM_SMEM);
        cudaFuncSetAttribute(f16_gemm_bias<0>,
                             cudaFuncAttributeMaxDynamicSharedMemorySize, HGEMM_SMEM);
        configured = 1;
    }

    // 0) prep: fp32 -> fp16 conversions
    f2h_kernel<<<1024, 256>>>(x, xh, (PB * PS * PD) / 4);
    f2h_kernel<<<512, 256>>>(W_qkv, wqh, (PD * 3 * PD) / 4);
    f2h_kernel<<<256, 256>>>(W_out, woh, (PD * PD) / 4);

    // 1) QKV projection: [8192,1024] @ [1024,3072] + b -> half
    {
        dim3 grid(3 * PD / HBN, M / HBM);  // (24, 64)
        f16_gemm_bias<1><<<grid, 128, HGEMM_SMEM>>>(xh, wqh, b_qkv, qkvh,
                                                    M, 3 * PD, PD);
    }

    // 2) FP16 flash attention -> half
    {
        dim3 grid(PS / 128, PB * PH);
        flash_f16_kernel<<<grid, 256, FL_SMEM>>>(qkvh, attnh);
    }

    // 3) Output projection: [8192,1024] @ [1024,1024] + b -> fp32
    {
        dim3 grid(PD / HBN, M / HBM);  // (8, 64)
        f16_gemm_bias<0><<<grid, 128, HGEMM_SMEM>>>(attnh, woh, b_out, out,
                                                    M, PD, PD);
    }
}

// round 8
// speedup vs baseline: 7.9349x; 1.0315x over previous
#include <cuda_runtime.h>
#include <cuda_fp16.h>
#include <math.h>
#include <cstdint>

// Problem constants: B=8, S=1024, D=1024, H=16, dh=64
#define PB 8
#define PS 1024
#define PD 1024
#define PH 16
#define PDH 64

// Scratch (allocation-free rule: __device__ globals)
__device__ __half g_qkvh[(size_t)PB * PS * 3 * PD];   // 48 MB [B*S, 3D] half
__device__ __half g_attnh[(size_t)PB * PS * PD];      // 16 MB [B*S, D] half
__device__ __half g_xh[(size_t)PB * PS * PD];         // 16 MB x half
__device__ __half g_wqh[(size_t)PD * 3 * PD];         //  6 MB W_qkv half [K,N]
__device__ __half g_woh[(size_t)PD * PD];             //  2 MB W_out half [K,N]

// ---------------------------------------------------------------------------
// Helpers
// ---------------------------------------------------------------------------
__device__ __forceinline__ void cpa16(void* dst, const void* src) {
    uint32_t d = (uint32_t)__cvta_generic_to_shared(dst);
    asm volatile("cp.async.cg.shared.global [%0], [%1], 16;\n" :: "r"(d), "l"(src));
}
__device__ __forceinline__ void mma_f16(float c[4], const uint32_t a[4],
                                        uint32_t b0, uint32_t b1) {
    asm volatile(
        "mma.sync.aligned.m16n8k16.row.col.f32.f16.f16.f32 "
        "{%0,%1,%2,%3}, {%4,%5,%6,%7}, {%8,%9}, {%0,%1,%2,%3};\n"
        : "+f"(c[0]), "+f"(c[1]), "+f"(c[2]), "+f"(c[3])
        : "r"(a[0]), "r"(a[1]), "r"(a[2]), "r"(a[3]), "r"(b0), "r"(b1));
}
__device__ __forceinline__ void ldsm_x4(uint32_t r[4], const __half* p) {
    uint32_t addr = (uint32_t)__cvta_generic_to_shared(p);
    asm volatile("ldmatrix.sync.aligned.m8n8.x4.shared.b16 {%0,%1,%2,%3}, [%4];\n"
                 : "=r"(r[0]), "=r"(r[1]), "=r"(r[2]), "=r"(r[3]) : "r"(addr));
}
__device__ __forceinline__ void ldsm_x4_t(uint32_t r[4], const __half* p) {
    uint32_t addr = (uint32_t)__cvta_generic_to_shared(p);
    asm volatile("ldmatrix.sync.aligned.m8n8.x4.trans.shared.b16 {%0,%1,%2,%3}, [%4];\n"
                 : "=r"(r[0]), "=r"(r[1]), "=r"(r[2]), "=r"(r[3]) : "r"(addr));
}
__device__ __forceinline__ uint32_t pack_h2(float lo, float hi) {
    __half2 h = __floats2half2_rn(lo, hi);
    return *(uint32_t*)&h;
}

// ---------------------------------------------------------------------------
// Prep: fp32 -> fp16 conversion (float4 grid-stride)
// ---------------------------------------------------------------------------
__global__ void f2h_kernel(const float* __restrict__ in,
                           __half* __restrict__ out, int n4)
{
    int i = blockIdx.x * blockDim.x + threadIdx.x;
    for (; i < n4; i += gridDim.x * blockDim.x) {
        float4 v = ((const float4*)in)[i];
        __half2 h0 = __floats2half2_rn(v.x, v.y);
        __half2 h1 = __floats2half2_rn(v.z, v.w);
        ((__half2*)out)[2 * i]     = h0;
        ((__half2*)out)[2 * i + 1] = h1;
    }
}

// ---------------------------------------------------------------------------
// FP16 tensor-core GEMM with bias: C[M,N] = A[M,K] @ B[K,N] + bias[N]
// A half [M,K] row-major; B half [K,N] row-major (ldmatrix.trans fragments).
// 128 threads = 4 warps (2m x 2n), block tile 128x128, BK=32, warp 64x64.
// __launch_bounds__(128, 3): 3 CTAs/SM -> 3 warps/SMSP so barrier phases of
// different CTAs overlap and keep the HMMA pipe fed.
// OUTH=1 -> store half; OUTH=0 -> store fp32. 3-stage cp.async pipeline.
// ---------------------------------------------------------------------------
#define HBM 128
#define HBN 128
#define HBK 32
#define NSTAGE 3
#define HASTR 40     // halves (80B rows -> conflict-free ldmatrix)
#define HBSTR 136    // halves (272B rows -> conflict-free ldmatrix.trans)
#define HSTAGE_H (HBM * HASTR + HBK * HBSTR)      // 9472 halves
#define HGEMM_SMEM (NSTAGE * HSTAGE_H * 2)        // 56832 bytes

template<int OUTH>
__global__ __launch_bounds__(128, 3) void f16_gemm_bias(
    const __half* __restrict__ A, const __half* __restrict__ Bm,
    const float* __restrict__ bias, void* __restrict__ Cv,
    int M, int N, int K)
{
    extern __shared__ __half smh[];

    const int t    = threadIdx.x;
    const int w    = t >> 5;
    const int lane = t & 31;
    const int bm   = blockIdx.y * HBM;
    const int bn   = blockIdx.x * HBN;
    const int wm   = (w & 1) * 64;
    const int wn   = (w >> 1) * 64;
    const int r    = lane >> 2;
    const int q    = lane & 3;

    const int KT = K / HBK;

    auto stage = [&](int s, int buf) {
        __half* sa = smh + buf * HSTAGE_H;
        __half* sb = sa + HBM * HASTR;
        const __half* ga = A + (size_t)bm * K + s * HBK;
#pragma unroll
        for (int i = 0; i < 4; i++) {
            const int ch = t + i * 128;           // 0..511
            const int row = ch >> 2, c8 = (ch & 3) * 8;
            cpa16(sa + row * HASTR + c8, ga + (size_t)row * K + c8);
        }
        const __half* gb = Bm + (size_t)(s * HBK) * N + bn;
#pragma unroll
        for (int i = 0; i < 4; i++) {
            const int ch = t + i * 128;           // 0..511
            const int row = ch >> 4, c8 = (ch & 15) * 8;
            cpa16(sb + row * HBSTR + c8, gb + (size_t)row * N + c8);
        }
    };

    float c[4][8][4];
#pragma unroll
    for (int mf = 0; mf < 4; mf++)
#pragma unroll
        for (int nf = 0; nf < 8; nf++)
#pragma unroll
            for (int i = 0; i < 4; i++) c[mf][nf][i] = 0.f;

    stage(0, 0);
    asm volatile("cp.async.commit_group;\n");
    stage(1, 1);
    asm volatile("cp.async.commit_group;\n");

    // ldmatrix lane-address constants
    const int a_row  = lane & 15;                 // row within 16-row block
    const int a_kof  = (lane & 16) ? 8 : 0;       // k lo/hi 8
    const int b_krow = lane & 15;                 // k row within 16
    const int b_nof  = (lane & 16) ? 8 : 0;       // n lo/hi 8

    for (int s = 0; s < KT; s++) {
        const int buf = s % NSTAGE;
        if (s + 1 < KT) asm volatile("cp.async.wait_group 1;\n");
        else            asm volatile("cp.async.wait_group 0;\n");
        __syncthreads();
        if (s + 2 < KT) {
            stage(s + 2, (s + 2) % NSTAGE);
            asm volatile("cp.async.commit_group;\n");
        }

        const __half* sa = smh + buf * HSTAGE_H;
        const __half* sb = sa + HBM * HASTR;

#pragma unroll
        for (int kb = 0; kb < 2; kb++) {
            const int k0 = kb * 16;
            uint32_t a[4][4];
#pragma unroll
            for (int mf = 0; mf < 4; mf++)
                ldsm_x4(a[mf], sa + (wm + mf * 16 + a_row) * HASTR + k0 + a_kof);

            uint32_t bf[4][4];
#pragma unroll
            for (int ng = 0; ng < 4; ng++)
                ldsm_x4_t(bf[ng], sb + (k0 + b_krow) * HBSTR + wn + ng * 16 + b_nof);

#pragma unroll
            for (int ng = 0; ng < 4; ng++)
#pragma unroll
                for (int sub = 0; sub < 2; sub++) {
                    const int nf = ng * 2 + sub;
                    const uint32_t b0 = bf[ng][2 * sub], b1 = bf[ng][2 * sub + 1];
#pragma unroll
                    for (int mf = 0; mf < 4; mf++)
                        mma_f16(c[mf][nf], a[mf], b0, b1);
                }
        }
    }

    // epilogue with fp32 bias
#pragma unroll
    for (int mf = 0; mf < 4; mf++) {
        const int row0 = bm + wm + mf * 16 + r;
#pragma unroll
        for (int nf = 0; nf < 8; nf++) {
            const int col = bn + wn + nf * 8 + q * 2;
            float2 bi = *(const float2*)(bias + col);
            const float v00 = c[mf][nf][0] + bi.x, v01 = c[mf][nf][1] + bi.y;
            const float v10 = c[mf][nf][2] + bi.x, v11 = c[mf][nf][3] + bi.y;
            if (OUTH) {
                __half* C = (__half*)Cv;
                *(__half2*)(C + (size_t)row0 * N + col)       = __floats2half2_rn(v00, v01);
                *(__half2*)(C + (size_t)(row0 + 8) * N + col) = __floats2half2_rn(v10, v11);
            } else {
                float* C = (float*)Cv;
                *(float2*)(C + (size_t)row0 * N + col)       = make_float2(v00, v01);
                *(float2*)(C + (size_t)(row0 + 8) * N + col) = make_float2(v10, v11);
            }
        }
    }
}

// ---------------------------------------------------------------------------
// FP16 tensor-core flash attention (fp32 accum, causal) — unchanged.
// ---------------------------------------------------------------------------
#define FKSTR 72
#define FL_SMEM (2 * 64 * FKSTR * 2 * 2)   // bytes

__global__ __launch_bounds__(256) void flash_f16_kernel(
    const __half* __restrict__ qkv, __half* __restrict__ out)
{
    extern __shared__ __half smf[];
    __half* Ks = smf;                    // [2][64][FKSTR]
    __half* Vs = smf + 2 * 64 * FKSTR;   // [2][64][FKSTR]

    const int t    = threadIdx.x;
    const int w    = t >> 5;
    const int lane = t & 31;
    const int r    = lane >> 2;
    const int q    = lane & 3;
    const int qt   = blockIdx.x;
    const int bh   = blockIdx.y;
    const int b    = bh / PH;
    const int h    = bh % PH;

    const int qbase = qt * 128 + w * 16;
    const int RS = 3 * PD;  // 3072

    const __half* kbase = qkv + (size_t)(b * PS) * RS + PD + h * PDH;
    const __half* vbase = kbase + PD;

    // ---- Q fragments from gmem, scaled by 0.125 (exact pow2) ----
    uint32_t qa[4][4];
    {
        const __half* qp = qkv + (size_t)(b * PS + qbase) * RS + h * PDH;
        const __half2 scl = __float2half2_rn(0.125f);
#pragma unroll
        for (int kb = 0; kb < 4; kb++) {
            const int c0 = kb * 16 + 2 * q;
            uint32_t raw[4];
            raw[0] = *(const uint32_t*)(qp + (size_t)r * RS + c0);
            raw[1] = *(const uint32_t*)(qp + (size_t)(r + 8) * RS + c0);
            raw[2] = *(const uint32_t*)(qp + (size_t)r * RS + c0 + 8);
            raw[3] = *(const uint32_t*)(qp + (size_t)(r + 8) * RS + c0 + 8);
#pragma unroll
            for (int i = 0; i < 4; i++) {
                __half2 hh = __hmul2(*(__half2*)&raw[i], scl);
                qa[kb][i] = *(uint32_t*)&hh;
            }
        }
    }

    float oc[8][4];
#pragma unroll
    for (int nf = 0; nf < 8; nf++)
#pragma unroll
        for (int i = 0; i < 4; i++) oc[nf][i] = 0.f;
    float m0 = -1e30f, m1 = -1e30f, l0 = 0.f, l1 = 0.f;

    const int nkt = 2 * qt + 2;

    auto stage = [&](int kt, int buf) {
        __half* ks = Ks + buf * 64 * FKSTR;
        __half* vs = Vs + buf * 64 * FKSTR;
#pragma unroll
        for (int i = 0; i < 2; i++) {
            const int ch = t + i * 256;           // 0..511
            const int row = ch >> 3, c8 = (ch & 7) * 8;
            const size_t go = (size_t)(kt * 64 + row) * RS + c8;
            cpa16(ks + row * FKSTR + c8, kbase + go);
            cpa16(vs + row * FKSTR + c8, vbase + go);
        }
    };

    stage(0, 0);
    asm volatile("cp.async.commit_group;\n");

    const int kj_of = (lane & 7) + ((lane & 16) ? 8 : 0);  // K (non-trans) j row
    const int kk_of = (lane & 8) ? 8 : 0;                  // K k lo/hi
    const int vj_of = lane & 15;                           // V (trans) j row
    const int vd_of = (lane & 16) ? 8 : 0;                 // V d lo/hi

    for (int kt = 0; kt < nkt; kt++) {
        const int buf = kt & 1;
        if (kt + 1 < nkt) {
            stage(kt + 1, buf ^ 1);
            asm volatile("cp.async.commit_group;\n");
            asm volatile("cp.async.wait_group 1;\n");
        } else {
            asm volatile("cp.async.wait_group 0;\n");
        }
        __syncthreads();

        const int gk0 = kt * 64;
        if (gk0 <= qbase + 15) {
            const __half* ks = Ks + buf * 64 * FKSTR;
            const __half* vs = Vs + buf * 64 * FKSTR;

            // ---- S = Q @ K^T ----
            float s[8][4];
#pragma unroll
            for (int nf = 0; nf < 8; nf++)
#pragma unroll
                for (int i = 0; i < 4; i++) s[nf][i] = 0.f;

#pragma unroll
            for (int kb = 0; kb < 4; kb++) {
                const int k0 = kb * 16;
#pragma unroll
                for (int jg = 0; jg < 4; jg++) {
                    uint32_t kb4[4];
                    ldsm_x4(kb4, ks + (jg * 16 + kj_of) * FKSTR + k0 + kk_of);
                    mma_f16(s[2 * jg],     qa[kb], kb4[0], kb4[1]);
                    mma_f16(s[2 * jg + 1], qa[kb], kb4[2], kb4[3]);
                }
            }

            // ---- causal mask ----
            if (gk0 + 63 > qbase) {
                const int gq0 = qbase + r;
                const int gq1 = gq0 + 8;
#pragma unroll
                for (int nf = 0; nf < 8; nf++) {
                    const int gk = gk0 + nf * 8 + 2 * q;
                    if (gk > gq0)     s[nf][0] = -1e30f;
                    if (gk + 1 > gq0) s[nf][1] = -1e30f;
                    if (gk > gq1)     s[nf][2] = -1e30f;
                    if (gk + 1 > gq1) s[nf][3] = -1e30f;
                }
            }

            // ---- online softmax ----
            float rm0 = s[0][0], rm1 = s[0][2];
#pragma unroll
            for (int nf = 0; nf < 8; nf++) {
                rm0 = fmaxf(rm0, fmaxf(s[nf][0], s[nf][1]));
                rm1 = fmaxf(rm1, fmaxf(s[nf][2], s[nf][3]));
            }
            rm0 = fmaxf(rm0, __shfl_xor_sync(0xffffffffu, rm0, 1));
            rm0 = fmaxf(rm0, __shfl_xor_sync(0xffffffffu, rm0, 2));
            rm1 = fmaxf(rm1, __shfl_xor_sync(0xffffffffu, rm1, 1));
            rm1 = fmaxf(rm1, __shfl_xor_sync(0xffffffffu, rm1, 2));
            const float mn0 = fmaxf(m0, rm0);
            const float mn1 = fmaxf(m1, rm1);
            const float corr0 = __expf(m0 - mn0);
            const float corr1 = __expf(m1 - mn1);
            float rs0 = 0.f, rs1 = 0.f;
#pragma unroll
            for (int nf = 0; nf < 8; nf++) {
                s[nf][0] = __expf(s[nf][0] - mn0);
                s[nf][1] = __expf(s[nf][1] - mn0);
                s[nf][2] = __expf(s[nf][2] - mn1);
                s[nf][3] = __expf(s[nf][3] - mn1);
                rs0 += s[nf][0] + s[nf][1];
                rs1 += s[nf][2] + s[nf][3];
            }
            rs0 += __shfl_xor_sync(0xffffffffu, rs0, 1);
            rs0 += __shfl_xor_sync(0xffffffffu, rs0, 2);
            rs1 += __shfl_xor_sync(0xffffffffu, rs1, 1);
            rs1 += __shfl_xor_sync(0xffffffffu, rs1, 2);
            l0 = l0 * corr0 + rs0;  m0 = mn0;
            l1 = l1 * corr1 + rs1;  m1 = mn1;
#pragma unroll
            for (int nf = 0; nf < 8; nf++) {
                oc[nf][0] *= corr0; oc[nf][1] *= corr0;
                oc[nf][2] *= corr1; oc[nf][3] *= corr1;
            }

            // ---- pack P into A fragments (register-only) ----
            uint32_t pa[4][4];
#pragma unroll
            for (int jb = 0; jb < 4; jb++) {
                pa[jb][0] = pack_h2(s[2 * jb][0],     s[2 * jb][1]);
                pa[jb][1] = pack_h2(s[2 * jb][2],     s[2 * jb][3]);
                pa[jb][2] = pack_h2(s[2 * jb + 1][0], s[2 * jb + 1][1]);
                pa[jb][3] = pack_h2(s[2 * jb + 1][2], s[2 * jb + 1][3]);
            }

            // ---- O += P @ V ----
#pragma unroll
            for (int jb = 0; jb < 4; jb++) {
#pragma unroll
                for (int dg = 0; dg < 4; dg++) {
                    uint32_t vb4[4];
                    ldsm_x4_t(vb4, vs + (jb * 16 + vj_of) * FKSTR + dg * 16 + vd_of);
                    mma_f16(oc[2 * dg],     pa[jb], vb4[0], vb4[1]);
                    mma_f16(oc[2 * dg + 1], pa[jb], vb4[2], vb4[3]);
                }
            }
        }
        __syncthreads();
    }

    // ---- epilogue: normalize, store half [B*S, D] ----
    const float inv0 = 1.f / l0;
    const float inv1 = 1.f / l1;
    __half* o0 = out + (size_t)(b * PS + qbase + r) * PD + h * PDH;
    __half* o1 = o0 + (size_t)8 * PD;
#pragma unroll
    for (int nf = 0; nf < 8; nf++) {
        const int col = nf * 8 + 2 * q;
        *(__half2*)(o0 + col) = __floats2half2_rn(oc[nf][0] * inv0, oc[nf][1] * inv0);
        *(__half2*)(o1 + col) = __floats2half2_rn(oc[nf][2] * inv1, oc[nf][3] * inv1);
    }
}

// ---------------------------------------------------------------------------
// kernel_launch
// ---------------------------------------------------------------------------
extern "C" void kernel_launch(void* const* d_in, const int* in_sizes, int n_in,
                              void* d_out, int out_size)
{
    const float* x     = (const float*)d_in[0];
    const float* W_qkv = (const float*)d_in[1];
    const float* b_qkv = (const float*)d_in[2];
    const float* W_out = (const float*)d_in[3];
    const float* b_out = (const float*)d_in[4];
    float* out = (float*)d_out;

    __half *qkvh, *attnh, *xh, *wqh, *woh;
    cudaGetSymbolAddress((void**)&qkvh,  g_qkvh);
    cudaGetSymbolAddress((void**)&attnh, g_attnh);
    cudaGetSymbolAddress((void**)&xh,    g_xh);
    cudaGetSymbolAddress((void**)&wqh,   g_wqh);
    cudaGetSymbolAddress((void**)&woh,   g_woh);

    const int M = PB * PS;  // 8192

    static int configured = 0;
    if (!configured) {
        cudaFuncSetAttribute(f16_gemm_bias<1>,
                             cudaFuncAttributeMaxDynamicSharedMemorySize, HGEMM_SMEM);
        cudaFuncSetAttribute(f16_gemm_bias<0>,
                             cudaFuncAttributeMaxDynamicSharedMemorySize, HGEMM_SMEM);
        configured = 1;
    }

    // 0) prep: fp32 -> fp16 conversions
    f2h_kernel<<<1024, 256>>>(x, xh, (PB * PS * PD) / 4);
    f2h_kernel<<<512, 256>>>(W_qkv, wqh, (PD * 3 * PD) / 4);
    f2h_kernel<<<256, 256>>>(W_out, woh, (PD * PD) / 4);

    // 1) QKV projection: [8192,1024] @ [1024,3072] + b -> half
    {
        dim3 grid(3 * PD / HBN, M / HBM);  // (24, 64)
        f16_gemm_bias<1><<<grid, 128, HGEMM_SMEM>>>(xh, wqh, b_qkv, qkvh,
                                                    M, 3 * PD, PD);
    }

    // 2) FP16 flash attention -> half
    {
        dim3 grid(PS / 128, PB * PH);
        flash_f16_kernel<<<grid, 256, FL_SMEM>>>(qkvh, attnh);
    }

    // 3) Output projection: [8192,1024] @ [1024,1024] + b -> fp32
    {
        dim3 grid(PD / HBN, M / HBM);  // (8, 64)
        f16_gemm_bias<0><<<grid, 128, HGEMM_SMEM>>>(attnh, woh, b_out, out,
                                                    M, PD, PD);
    }
}

// round 9
// speedup vs baseline: 8.5825x; 1.0816x over previous
#include <cuda_runtime.h>
#include <cuda_fp16.h>
#include <math.h>
#include <cstdint>

// Problem constants: B=8, S=1024, D=1024, H=16, dh=64
#define PB 8
#define PS 1024
#define PD 1024
#define PH 16
#define PDH 64

// Scratch (allocation-free rule: __device__ globals)
__device__ __half g_qkvh[(size_t)PB * PS * 3 * PD];   // 48 MB [B*S, 3D] half
__device__ __half g_attnh[(size_t)PB * PS * PD];      // 16 MB [B*S, D] half
__device__ __half g_xh[(size_t)PB * PS * PD];         // 16 MB x half
__device__ __half g_wqh[(size_t)PD * 3 * PD];         //  6 MB W_qkv half [K,N]
__device__ __half g_woh[(size_t)PD * PD];             //  2 MB W_out half [K,N]

// ---------------------------------------------------------------------------
// Helpers
// ---------------------------------------------------------------------------
__device__ __forceinline__ void cpa16(void* dst, const void* src) {
    uint32_t d = (uint32_t)__cvta_generic_to_shared(dst);
    asm volatile("cp.async.cg.shared.global [%0], [%1], 16;\n" :: "r"(d), "l"(src));
}
__device__ __forceinline__ void mma_f16(float c[4], const uint32_t a[4],
                                        uint32_t b0, uint32_t b1) {
    asm volatile(
        "mma.sync.aligned.m16n8k16.row.col.f32.f16.f16.f32 "
        "{%0,%1,%2,%3}, {%4,%5,%6,%7}, {%8,%9}, {%0,%1,%2,%3};\n"
        : "+f"(c[0]), "+f"(c[1]), "+f"(c[2]), "+f"(c[3])
        : "r"(a[0]), "r"(a[1]), "r"(a[2]), "r"(a[3]), "r"(b0), "r"(b1));
}
__device__ __forceinline__ void ldsm_x4(uint32_t r[4], const __half* p) {
    uint32_t addr = (uint32_t)__cvta_generic_to_shared(p);
    asm volatile("ldmatrix.sync.aligned.m8n8.x4.shared.b16 {%0,%1,%2,%3}, [%4];\n"
                 : "=r"(r[0]), "=r"(r[1]), "=r"(r[2]), "=r"(r[3]) : "r"(addr));
}
__device__ __forceinline__ void ldsm_x4_t(uint32_t r[4], const __half* p) {
    uint32_t addr = (uint32_t)__cvta_generic_to_shared(p);
    asm volatile("ldmatrix.sync.aligned.m8n8.x4.trans.shared.b16 {%0,%1,%2,%3}, [%4];\n"
                 : "=r"(r[0]), "=r"(r[1]), "=r"(r[2]), "=r"(r[3]) : "r"(addr));
}
__device__ __forceinline__ uint32_t pack_h2(float lo, float hi) {
    __half2 h = __floats2half2_rn(lo, hi);
    return *(uint32_t*)&h;
}

// ---------------------------------------------------------------------------
// Prep: all three fp32 -> fp16 conversions in one grid-stride kernel
// ---------------------------------------------------------------------------
__global__ void prep_all_kernel(const float* __restrict__ x,
                                const float* __restrict__ wq,
                                const float* __restrict__ wo,
                                __half* __restrict__ xh,
                                __half* __restrict__ wqh,
                                __half* __restrict__ woh)
{
    const int n_x = (PB * PS * PD) / 4;        // 2097152 float4s
    const int n_q = (PD * 3 * PD) / 4;         // 786432
    const int n_o = (PD * PD) / 4;             // 262144
    const int total = n_x + n_q + n_o;
    int i = blockIdx.x * blockDim.x + threadIdx.x;
    for (; i < total; i += gridDim.x * blockDim.x) {
        const float* in; __half* out; int j;
        if (i < n_x)            { in = x;  out = xh;  j = i; }
        else if (i < n_x + n_q) { in = wq; out = wqh; j = i - n_x; }
        else                    { in = wo; out = woh; j = i - n_x - n_q; }
        float4 v = ((const float4*)in)[j];
        ((__half2*)out)[2 * j]     = __floats2half2_rn(v.x, v.y);
        ((__half2*)out)[2 * j + 1] = __floats2half2_rn(v.z, v.w);
    }
}

// ---------------------------------------------------------------------------
// FP16 tensor-core GEMM with bias: C[M,N] = A[M,K] @ B[K,N] + bias[N]
// 128 threads = 4 warps (2m x 2n), block tile 128x128, BK=32, warp 64x64.
// NSTAGE=4 cp.async pipeline + register double-buffered fragments: frags for
// the NEXT k16 step (incl. across the s-boundary) are loaded while current
// mmas run, so only the bare barrier interrupts the HMMA stream.
// ---------------------------------------------------------------------------
#define HBM 128
#define HBN 128
#define HBK 32
#define NSTAGE 4
#define HASTR 40     // halves (80B rows -> conflict-free ldmatrix)
#define HBSTR 136    // halves (272B rows -> conflict-free ldmatrix.trans)
#define HSTAGE_H (HBM * HASTR + HBK * HBSTR)      // 9472 halves
#define HGEMM_SMEM (NSTAGE * HSTAGE_H * 2)        // 75776 bytes

template<int OUTH>
__global__ __launch_bounds__(128, 2) void f16_gemm_bias(
    const __half* __restrict__ A, const __half* __restrict__ Bm,
    const float* __restrict__ bias, void* __restrict__ Cv,
    int M, int N, int K)
{
    extern __shared__ __half smh[];

    const int t    = threadIdx.x;
    const int w    = t >> 5;
    const int lane = t & 31;
    const int bm   = blockIdx.y * HBM;
    const int bn   = blockIdx.x * HBN;
    const int wm   = (w & 1) * 64;
    const int wn   = (w >> 1) * 64;
    const int r    = lane >> 2;
    const int q    = lane & 3;

    const int KT = K / HBK;   // 32

    auto stage = [&](int s, int buf) {
        __half* sa = smh + buf * HSTAGE_H;
        __half* sb = sa + HBM * HASTR;
        const __half* ga = A + (size_t)bm * K + s * HBK;
#pragma unroll
        for (int i = 0; i < 4; i++) {
            const int ch = t + i * 128;           // 0..511
            const int row = ch >> 2, c8 = (ch & 3) * 8;
            cpa16(sa + row * HASTR + c8, ga + (size_t)row * K + c8);
        }
        const __half* gb = Bm + (size_t)(s * HBK) * N + bn;
#pragma unroll
        for (int i = 0; i < 4; i++) {
            const int ch = t + i * 128;           // 0..511
            const int row = ch >> 4, c8 = (ch & 15) * 8;
            cpa16(sb + row * HBSTR + c8, gb + (size_t)row * N + c8);
        }
    };

    float c[4][8][4];
#pragma unroll
    for (int mf = 0; mf < 4; mf++)
#pragma unroll
        for (int nf = 0; nf < 8; nf++)
#pragma unroll
            for (int i = 0; i < 4; i++) c[mf][nf][i] = 0.f;

    stage(0, 0);
    asm volatile("cp.async.commit_group;\n");
    stage(1, 1);
    asm volatile("cp.async.commit_group;\n");
    stage(2, 2);
    asm volatile("cp.async.commit_group;\n");

    // ldmatrix lane-address constants
    const int a_row  = lane & 15;
    const int a_kof  = (lane & 16) ? 8 : 0;
    const int b_krow = lane & 15;
    const int b_nof  = (lane & 16) ? 8 : 0;

    // register double-buffered fragment sets
    uint32_t af[2][4][4], bf[2][4][4];

    auto load_frags = [&](int p, const __half* sa, const __half* sb, int k0) {
#pragma unroll
        for (int mf = 0; mf < 4; mf++)
            ldsm_x4(af[p][mf], sa + (wm + mf * 16 + a_row) * HASTR + k0 + a_kof);
#pragma unroll
        for (int ng = 0; ng < 4; ng++)
            ldsm_x4_t(bf[p][ng], sb + (k0 + b_krow) * HBSTR + wn + ng * 16 + b_nof);
    };
    auto do_mma = [&](int p) {
#pragma unroll
        for (int ng = 0; ng < 4; ng++)
#pragma unroll
            for (int sub = 0; sub < 2; sub++) {
                const int nf = ng * 2 + sub;
#pragma unroll
                for (int mf = 0; mf < 4; mf++)
                    mma_f16(c[mf][nf], af[p][mf],
                            bf[p][ng][2 * sub], bf[p][ng][2 * sub + 1]);
            }
    };

    // prologue: stages 0,1 landed + visible, preload (s=0, kb0)
    asm volatile("cp.async.wait_group 1;\n");
    __syncthreads();
    load_frags(0, smh, smh + HBM * HASTR, 0);
    int p = 0;

    for (int s = 0; s < KT; s++) {
        const __half* sa = smh + (s & 3) * HSTAGE_H;
        const __half* sb = sa + HBM * HASTR;

        if (s + 3 < KT) {                       // overwrite buf (s-1)&3: safe after
            stage(s + 3, (s + 3) & 3);          // last iteration's barrier
            asm volatile("cp.async.commit_group;\n");
        }

        load_frags(p ^ 1, sa, sb, 16);          // (s, kb1) — stage s landed
        do_mma(p);                              // (s, kb0)
        p ^= 1;

        if (s + 1 < KT) {
            const __half* na = smh + ((s + 1) & 3) * HSTAGE_H;
            load_frags(p ^ 1, na, na + HBM * HASTR, 0);  // (s+1, kb0) — landed
        }
        do_mma(p);                              // (s, kb1)
        p ^= 1;

        if (s + 1 < KT) {
            asm volatile("cp.async.wait_group 1;\n");    // stages <= s+2 done
            __syncthreads();                             // visibility + WAR guard
        }
    }

    // epilogue with fp32 bias
#pragma unroll
    for (int mf = 0; mf < 4; mf++) {
        const int row0 = bm + wm + mf * 16 + r;
#pragma unroll
        for (int nf = 0; nf < 8; nf++) {
            const int col = bn + wn + nf * 8 + q * 2;
            float2 bi = *(const float2*)(bias + col);
            const float v00 = c[mf][nf][0] + bi.x, v01 = c[mf][nf][1] + bi.y;
            const float v10 = c[mf][nf][2] + bi.x, v11 = c[mf][nf][3] + bi.y;
            if (OUTH) {
                __half* C = (__half*)Cv;
                *(__half2*)(C + (size_t)row0 * N + col)       = __floats2half2_rn(v00, v01);
                *(__half2*)(C + (size_t)(row0 + 8) * N + col) = __floats2half2_rn(v10, v11);
            } else {
                float* C = (float*)Cv;
                *(float2*)(C + (size_t)row0 * N + col)       = make_float2(v00, v01);
                *(float2*)(C + (size_t)(row0 + 8) * N + col) = make_float2(v10, v11);
            }
        }
    }
}

// ---------------------------------------------------------------------------
// FP16 tensor-core flash attention (fp32 accum, causal).
// 128-thread blocks (4 warps, qtile 64) with __launch_bounds__(128,3):
// 3 independent CTAs/SM so barrier phases interleave across CTAs.
// Softmax in exp2 domain: Q pre-scaled by 0.125*log2(e).
// Grid (16 qtiles, 128 b*h). smem: K[2][64][72] + V[2][64][72] halves.
// ---------------------------------------------------------------------------
#define FKSTR 72
#define FL_SMEM (2 * 64 * FKSTR * 2 * 2)   // 36864 bytes

__global__ __launch_bounds__(128, 3) void flash_f16_kernel(
    const __half* __restrict__ qkv, __half* __restrict__ out)
{
    extern __shared__ __half smf[];
    __half* Ks = smf;                    // [2][64][FKSTR]
    __half* Vs = smf + 2 * 64 * FKSTR;   // [2][64][FKSTR]

    const int t    = threadIdx.x;
    const int w    = t >> 5;             // 0..3
    const int lane = t & 31;
    const int r    = lane >> 2;
    const int q    = lane & 3;
    const int qt   = blockIdx.x;         // 0..15
    const int bh   = blockIdx.y;
    const int b    = bh / PH;
    const int h    = bh % PH;

    const int qbase = qt * 64 + w * 16;
    const int RS = 3 * PD;  // 3072

    const __half* kbase = qkv + (size_t)(b * PS) * RS + PD + h * PDH;
    const __half* vbase = kbase + PD;

    // ---- Q fragments from gmem, scaled by 0.125*log2(e) (exp2 domain) ----
    uint32_t qa[4][4];
    {
        const __half* qp = qkv + (size_t)(b * PS + qbase) * RS + h * PDH;
        const __half2 scl = __float2half2_rn(0.18033688f);  // 0.125*log2e
#pragma unroll
        for (int kb = 0; kb < 4; kb++) {
            const int c0 = kb * 16 + 2 * q;
            uint32_t raw[4];
            raw[0] = *(const uint32_t*)(qp + (size_t)r * RS + c0);
            raw[1] = *(const uint32_t*)(qp + (size_t)(r + 8) * RS + c0);
            raw[2] = *(const uint32_t*)(qp + (size_t)r * RS + c0 + 8);
            raw[3] = *(const uint32_t*)(qp + (size_t)(r + 8) * RS + c0 + 8);
#pragma unroll
            for (int i = 0; i < 4; i++) {
                __half2 hh = __hmul2(*(__half2*)&raw[i], scl);
                qa[kb][i] = *(uint32_t*)&hh;
            }
        }
    }

    float oc[8][4];
#pragma unroll
    for (int nf = 0; nf < 8; nf++)
#pragma unroll
        for (int i = 0; i < 4; i++) oc[nf][i] = 0.f;
    float m0 = -1e30f, m1 = -1e30f, l0 = 0.f, l1 = 0.f;

    const int nkt = qt + 1;

    auto stage = [&](int kt, int buf) {
        __half* ks = Ks + buf * 64 * FKSTR;
        __half* vs = Vs + buf * 64 * FKSTR;
#pragma unroll
        for (int i = 0; i < 4; i++) {
            const int ch = t + i * 128;           // 0..511
            const int row = ch >> 3, c8 = (ch & 7) * 8;
            const size_t go = (size_t)(kt * 64 + row) * RS + c8;
            cpa16(ks + row * FKSTR + c8, kbase + go);
            cpa16(vs + row * FKSTR + c8, vbase + go);
        }
    };

    stage(0, 0);
    asm volatile("cp.async.commit_group;\n");

    const int kj_of = (lane & 7) + ((lane & 16) ? 8 : 0);  // K (non-trans) j row
    const int kk_of = (lane & 8) ? 8 : 0;                  // K k lo/hi
    const int vj_of = lane & 15;                           // V (trans) j row
    const int vd_of = (lane & 16) ? 8 : 0;                 // V d lo/hi

    for (int kt = 0; kt < nkt; kt++) {
        const int buf = kt & 1;
        if (kt + 1 < nkt) {
            stage(kt + 1, buf ^ 1);
            asm volatile("cp.async.commit_group;\n");
            asm volatile("cp.async.wait_group 1;\n");
        } else {
            asm volatile("cp.async.wait_group 0;\n");
        }
        __syncthreads();

        const int gk0 = kt * 64;
        {
            const __half* ks = Ks + buf * 64 * FKSTR;
            const __half* vs = Vs + buf * 64 * FKSTR;

            // ---- S' = (Q*0.125*log2e) @ K^T ----
            float s[8][4];
#pragma unroll
            for (int nf = 0; nf < 8; nf++)
#pragma unroll
                for (int i = 0; i < 4; i++) s[nf][i] = 0.f;

#pragma unroll
            for (int kb = 0; kb < 4; kb++) {
                const int k0 = kb * 16;
#pragma unroll
                for (int jg = 0; jg < 4; jg++) {
                    uint32_t kb4[4];
                    ldsm_x4(kb4, ks + (jg * 16 + kj_of) * FKSTR + k0 + kk_of);
                    mma_f16(s[2 * jg],     qa[kb], kb4[0], kb4[1]);
                    mma_f16(s[2 * jg + 1], qa[kb], kb4[2], kb4[3]);
                }
            }

            // ---- causal mask (diagonal tile only: kt == qt) ----
            if (kt == qt) {
                const int gq0 = qbase + r;
                const int gq1 = gq0 + 8;
#pragma unroll
                for (int nf = 0; nf < 8; nf++) {
                    const int gk = gk0 + nf * 8 + 2 * q;
                    if (gk > gq0)     s[nf][0] = -1e30f;
                    if (gk + 1 > gq0) s[nf][1] = -1e30f;
                    if (gk > gq1)     s[nf][2] = -1e30f;
                    if (gk + 1 > gq1) s[nf][3] = -1e30f;
                }
            }

            // ---- online softmax (exp2 domain) ----
            float rm0 = s[0][0], rm1 = s[0][2];
#pragma unroll
            for (int nf = 0; nf < 8; nf++) {
                rm0 = fmaxf(rm0, fmaxf(s[nf][0], s[nf][1]));
                rm1 = fmaxf(rm1, fmaxf(s[nf][2], s[nf][3]));
            }
            rm0 = fmaxf(rm0, __shfl_xor_sync(0xffffffffu, rm0, 1));
            rm0 = fmaxf(rm0, __shfl_xor_sync(0xffffffffu, rm0, 2));
            rm1 = fmaxf(rm1, __shfl_xor_sync(0xffffffffu, rm1, 1));
            rm1 = fmaxf(rm1, __shfl_xor_sync(0xffffffffu, rm1, 2));
            const float mn0 = fmaxf(m0, rm0);
            const float mn1 = fmaxf(m1, rm1);
            const float corr0 = exp2f(m0 - mn0);
            const float corr1 = exp2f(m1 - mn1);
            float rs0 = 0.f, rs1 = 0.f;
#pragma unroll
            for (int nf = 0; nf < 8; nf++) {
                s[nf][0] = exp2f(s[nf][0] - mn0);
                s[nf][1] = exp2f(s[nf][1] - mn0);
                s[nf][2] = exp2f(s[nf][2] - mn1);
                s[nf][3] = exp2f(s[nf][3] - mn1);
                rs0 += s[nf][0] + s[nf][1];
                rs1 += s[nf][2] + s[nf][3];
            }
            rs0 += __shfl_xor_sync(0xffffffffu, rs0, 1);
            rs0 += __shfl_xor_sync(0xffffffffu, rs0, 2);
            rs1 += __shfl_xor_sync(0xffffffffu, rs1, 1);
            rs1 += __shfl_xor_sync(0xffffffffu, rs1, 2);
            l0 = l0 * corr0 + rs0;  m0 = mn0;
            l1 = l1 * corr1 + rs1;  m1 = mn1;
#pragma unroll
            for (int nf = 0; nf < 8; nf++) {
                oc[nf][0] *= corr0; oc[nf][1] *= corr0;
                oc[nf][2] *= corr1; oc[nf][3] *= corr1;
            }

            // ---- pack P into A fragments (register-only) ----
            uint32_t pa[4][4];
#pragma unroll
            for (int jb = 0; jb < 4; jb++) {
                pa[jb][0] = pack_h2(s[2 * jb][0],     s[2 * jb][1]);
                pa[jb][1] = pack_h2(s[2 * jb][2],     s[2 * jb][3]);
                pa[jb][2] = pack_h2(s[2 * jb + 1][0], s[2 * jb + 1][1]);
                pa[jb][3] = pack_h2(s[2 * jb + 1][2], s[2 * jb + 1][3]);
            }

            // ---- O += P @ V ----
#pragma unroll
            for (int jb = 0; jb < 4; jb++) {
#pragma unroll
                for (int dg = 0; dg < 4; dg++) {
                    uint32_t vb4[4];
                    ldsm_x4_t(vb4, vs + (jb * 16 + vj_of) * FKSTR + dg * 16 + vd_of);
                    mma_f16(oc[2 * dg],     pa[jb], vb4[0], vb4[1]);
                    mma_f16(oc[2 * dg + 1], pa[jb], vb4[2], vb4[3]);
                }
            }
        }
        __syncthreads();
    }

    // ---- epilogue: normalize, store half [B*S, D] ----
    const float inv0 = 1.f / l0;
    const float inv1 = 1.f / l1;
    __half* o0 = out + (size_t)(b * PS + qbase + r) * PD + h * PDH;
    __half* o1 = o0 + (size_t)8 * PD;
#pragma unroll
    for (int nf = 0; nf < 8; nf++) {
        const int col = nf * 8 + 2 * q;
        *(__half2*)(o0 + col) = __floats2half2_rn(oc[nf][0] * inv0, oc[nf][1] * inv0);
        *(__half2*)(o1 + col) = __floats2half2_rn(oc[nf][2] * inv1, oc[nf][3] * inv1);
    }
}

// ---------------------------------------------------------------------------
// kernel_launch
// ---------------------------------------------------------------------------
extern "C" void kernel_launch(void* const* d_in, const int* in_sizes, int n_in,
                              void* d_out, int out_size)
{
    const float* x     = (const float*)d_in[0];
    const float* W_qkv = (const float*)d_in[1];
    const float* b_qkv = (const float*)d_in[2];
    const float* W_out = (const float*)d_in[3];
    const float* b_out = (const float*)d_in[4];
    float* out = (float*)d_out;

    __half *qkvh, *attnh, *xh, *wqh, *woh;
    cudaGetSymbolAddress((void**)&qkvh,  g_qkvh);
    cudaGetSymbolAddress((void**)&attnh, g_attnh);
    cudaGetSymbolAddress((void**)&xh,    g_xh);
    cudaGetSymbolAddress((void**)&wqh,   g_wqh);
    cudaGetSymbolAddress((void**)&woh,   g_woh);

    const int M = PB * PS;  // 8192

    static int configured = 0;
    if (!configured) {
        cudaFuncSetAttribute(f16_gemm_bias<1>,
                             cudaFuncAttributeMaxDynamicSharedMemorySize, HGEMM_SMEM);
        cudaFuncSetAttribute(f16_gemm_bias<0>,
                             cudaFuncAttributeMaxDynamicSharedMemorySize, HGEMM_SMEM);
        cudaFuncSetAttribute(flash_f16_kernel,
                             cudaFuncAttributeMaxDynamicSharedMemorySize, FL_SMEM);
        configured = 1;
    }

    // 0) prep: single fused fp32 -> fp16 conversion pass
    prep_all_kernel<<<2048, 256>>>(x, W_qkv, W_out, xh, wqh, woh);

    // 1) QKV projection: [8192,1024] @ [1024,3072] + b -> half
    {
        dim3 grid(3 * PD / HBN, M / HBM);  // (24, 64)
        f16_gemm_bias<1><<<grid, 128, HGEMM_SMEM>>>(xh, wqh, b_qkv, qkvh,
                                                    M, 3 * PD, PD);
    }

    // 2) FP16 flash attention -> half
    {
        dim3 grid(PS / 64, PB * PH);       // (16, 128)
        flash_f16_kernel<<<grid, 128, FL_SMEM>>>(qkvh, attnh);
    }

    // 3) Output projection: [8192,1024] @ [1024,1024] + b -> fp32
    {
        dim3 grid(PD / HBN, M / HBM);      // (8, 64)
        f16_gemm_bias<0><<<grid, 128, HGEMM_SMEM>>>(attnh, woh, b_out, out,
                                                    M, PD, PD);
    }
}